// round 6
// baseline (speedup 1.0000x reference)
#include <cuda_runtime.h>
#include <cuda_bf16.h>
#include <math.h>
#include <stdint.h>

#define NQ 8192
#define DQ 128
#define EQ 262144
#define EDIM 50
#define HID 32

// ---------------- scratch (device globals: no allocation allowed) ----------------
__device__ float          g_scores [(size_t)NQ * NQ];    // 256 MiB fp32 logits
__device__ __nv_bfloat16  g_attn_hi[(size_t)NQ * NQ];    // 128 MiB
__device__ __nv_bfloat16  g_attn_lo[(size_t)NQ * NQ];    // 128 MiB
__device__ __nv_bfloat16  g_ab_hi  [(size_t)NQ * 256];   // [N][a|b], K=256
__device__ __nv_bfloat16  g_ab_lo  [(size_t)NQ * 256];
__device__ __nv_bfloat16  g_mpT_hi [(size_t)256 * NQ];   // [mag|phase]^T
__device__ __nv_bfloat16  g_mpT_lo [(size_t)256 * NQ];

__device__ __forceinline__ void split_bf16(float x, __nv_bfloat16& hi, __nv_bfloat16& lo) {
    hi = __float2bfloat16(x);
    lo = __float2bfloat16(x - __bfloat162float(hi));
}

__device__ __forceinline__ uint32_t smem_u32(const void* p) {
    uint32_t a;
    asm("{ .reg .u64 t; cvta.to.shared.u64 t, %1; cvt.u32.u64 %0, t; }" : "=r"(a) : "l"(p));
    return a;
}
__device__ __forceinline__ void cp_async16(void* sdst, const void* gsrc) {
    unsigned s = (unsigned)__cvta_generic_to_shared(sdst);
    asm volatile("cp.async.cg.shared.global [%0], [%1], 16;\n" :: "r"(s), "l"(gsrc));
}
#define CP_COMMIT() asm volatile("cp.async.commit_group;\n" ::: "memory")
#define CP_WAIT1()  asm volatile("cp.async.wait_group 1;\n" ::: "memory")

__device__ __forceinline__ void ldmx4(uint32_t* r, uint32_t addr) {
    asm volatile("ldmatrix.sync.aligned.m8n8.x4.shared.b16 {%0,%1,%2,%3}, [%4];"
                 : "=r"(r[0]), "=r"(r[1]), "=r"(r[2]), "=r"(r[3]) : "r"(addr));
}

// ---------------- K1: prep a,b (hi/lo) and transposed mag/phase (hi/lo) ----------------
__global__ void prep_kernel(const float* __restrict__ mag, const float* __restrict__ phase) {
    int idx = blockIdx.x * blockDim.x + threadIdx.x;   // < N*D
    int i = idx >> 7;
    int d = idx & 127;
    float m = mag[idx];
    float p = phase[idx];
    float s, c;
    __sincosf(p, &s, &c);
    __nv_bfloat16 h, l;
    split_bf16(m * c, h, l);
    g_ab_hi[(size_t)i * 256 + d] = h;  g_ab_lo[(size_t)i * 256 + d] = l;
    split_bf16(m * s, h, l);
    g_ab_hi[(size_t)i * 256 + 128 + d] = h;  g_ab_lo[(size_t)i * 256 + 128 + d] = l;
    split_bf16(m, h, l);
    g_mpT_hi[(size_t)d * NQ + i] = h;  g_mpT_lo[(size_t)d * NQ + i] = l;
    split_bf16(p, h, l);
    g_mpT_hi[(size_t)(128 + d) * NQ + i] = h;  g_mpT_lo[(size_t)(128 + d) * NQ + i] = l;
}

// ---------------- GEMM: C[M,N] = (Ahi+Alo)[M,K] * (Bhi+Blo)[N,K]^T, 3-term bf16 split ----
// BM=BN=128, BK=32, 256 threads, 8 warps 2x4, warp tile 64x32, mma m16n8k16, ldmatrix frags
// cp.async 2-stage double buffer; dynamic smem 80 KB; 2 CTAs/SM.
// MODE 0: A=B=g_ab (K=256), C=g_scores scaled; SYMMETRIC: bm<=bn tiles only + mirror store.
// MODE 1: A=g_attn, B=g_mpT (K=8192, split-K z=2), atomicAdd into Cout
#define TSTRIDE 40
#define TSZ (128 * TSTRIDE)            // elems per tensor tile
#define TSZB (TSZ * 2)                 // 10240 B
#define STAGEB (4 * TSZB)              // 40960 B

template <int MODE>
__global__ __launch_bounds__(256, 2)
void gemm_kernel(float* __restrict__ Cout, float scale) {
    extern __shared__ __align__(16) __nv_bfloat16 dsm[];   // [2][4][128][40]

    const int bm = blockIdx.y, bn = blockIdx.x;
    if (MODE == 0 && bn < bm) return;   // symmetric: upper-triangle tiles only

    const int K = (MODE == 0) ? 256 : NQ;
    const __nv_bfloat16* Ahi = (MODE == 0) ? g_ab_hi : g_attn_hi;
    const __nv_bfloat16* Alo = (MODE == 0) ? g_ab_lo : g_attn_lo;
    const __nv_bfloat16* Bhi = (MODE == 0) ? g_ab_hi : g_mpT_hi;
    const __nv_bfloat16* Blo = (MODE == 0) ? g_ab_lo : g_mpT_lo;

    const int tid = threadIdx.x;
    const int warp = tid >> 5, lane = tid & 31;
    const int wm = warp >> 2, wn = warp & 3;
    const int g = lane >> 2, q = lane & 3;

    float acc[4][4][4];
#pragma unroll
    for (int mi = 0; mi < 4; mi++)
#pragma unroll
        for (int ni = 0; ni < 4; ni++)
#pragma unroll
            for (int r = 0; r < 4; r++) acc[mi][ni][r] = 0.f;

    const __nv_bfloat16* Abh = Ahi + (size_t)bm * 128 * K;
    const __nv_bfloat16* Abl = Alo + (size_t)bm * 128 * K;
    const __nv_bfloat16* Bbh = Bhi + (size_t)bn * 128 * K;
    const __nv_bfloat16* Bbl = Blo + (size_t)bn * 128 * K;

    const int kbeg = (MODE == 0) ? 0 : blockIdx.z * (NQ / 2);
    const int nit = ((MODE == 0) ? 256 : NQ / 2) / 32;

    const int lr = tid >> 2;        // 0..63
    const int lc = (tid & 3) * 8;   // bf16 col of uint4

    // ldmatrix per-lane byte offsets within a [128][TSTRIDE] tile
    const int xr = lane & 7;               // row within 8x8 matrix
    const int xb = (lane >> 3) & 1;        // +8-row block (matrix 1/3)
    const int xk = (lane >> 4) & 1;        // +16B k-half (matrix 2/3)
    uint32_t aoff[4], boff[2];
#pragma unroll
    for (int mi = 0; mi < 4; mi++)
        aoff[mi] = (uint32_t)((wm * 64 + mi * 16 + xb * 8 + xr) * (TSTRIDE * 2) + xk * 16);
#pragma unroll
    for (int pi = 0; pi < 2; pi++)
        boff[pi] = (uint32_t)((wn * 32 + pi * 16 + xb * 8 + xr) * (TSTRIDE * 2) + xk * 16);

    const uint32_t smbase = smem_u32(dsm);

#define PREFETCH(IT, ST)                                                         \
    do {                                                                         \
        int k0_ = kbeg + (IT) * 32;                                              \
        __nv_bfloat16* d_ = dsm + (ST) * 4 * TSZ;                                \
        _Pragma("unroll")                                                        \
        for (int hf = 0; hf < 2; hf++) {                                         \
            int r_ = lr + hf * 64;                                               \
            size_t go_ = (size_t)r_ * K + k0_ + lc;                              \
            int so_ = r_ * TSTRIDE + lc;                                         \
            cp_async16(d_ + 0 * TSZ + so_, Abh + go_);                           \
            cp_async16(d_ + 1 * TSZ + so_, Abl + go_);                           \
            cp_async16(d_ + 2 * TSZ + so_, Bbh + go_);                           \
            cp_async16(d_ + 3 * TSZ + so_, Bbl + go_);                           \
        }                                                                        \
    } while (0)

    PREFETCH(0, 0);
    CP_COMMIT();

    for (int it = 0; it < nit; it++) {
        if (it + 1 < nit) PREFETCH(it + 1, (it + 1) & 1);
        CP_COMMIT();
        CP_WAIT1();
        __syncthreads();

        const uint32_t SAh = smbase + (uint32_t)(it & 1) * STAGEB;
        const uint32_t SAl = SAh + TSZB;
        const uint32_t SBh = SAh + 2 * TSZB;
        const uint32_t SBl = SAh + 3 * TSZB;

#pragma unroll
        for (int kk = 0; kk < 2; kk++) {
            uint32_t rah[4][4], ral[4][4], rbh[2][4], rbl[2][4];
            const uint32_t kb = kk * 32;
#pragma unroll
            for (int mi = 0; mi < 4; mi++) {
                ldmx4(rah[mi], SAh + aoff[mi] + kb);
                ldmx4(ral[mi], SAl + aoff[mi] + kb);
            }
#pragma unroll
            for (int pi = 0; pi < 2; pi++) {
                ldmx4(rbh[pi], SBh + boff[pi] + kb);
                ldmx4(rbl[pi], SBl + boff[pi] + kb);
            }
#define MMA4(AC, AA, B0, B1)                                                       \
    asm volatile(                                                                  \
        "mma.sync.aligned.m16n8k16.row.col.f32.bf16.bf16.f32 "                     \
        "{%0,%1,%2,%3}, {%4,%5,%6,%7}, {%8,%9}, {%0,%1,%2,%3};\n"                  \
        : "+f"((AC)[0]), "+f"((AC)[1]), "+f"((AC)[2]), "+f"((AC)[3])               \
        : "r"((AA)[0]), "r"((AA)[1]), "r"((AA)[2]), "r"((AA)[3]),                  \
          "r"(B0), "r"(B1))
#pragma unroll
            for (int mi = 0; mi < 4; mi++)
#pragma unroll
                for (int ni = 0; ni < 4; ni++) {
                    const int pi = ni >> 1, h = ni & 1;
                    MMA4(acc[mi][ni], rah[mi], rbh[pi][h], rbh[pi][h + 2]);
                    MMA4(acc[mi][ni], rah[mi], rbl[pi][h], rbl[pi][h + 2]);
                    MMA4(acc[mi][ni], ral[mi], rbh[pi][h], rbh[pi][h + 2]);
                }
#undef MMA4
        }
        __syncthreads();
    }
#undef PREFETCH

    // epilogue
#pragma unroll
    for (int mi = 0; mi < 4; mi++) {
        int r0 = bm * 128 + wm * 64 + mi * 16 + g;
#pragma unroll
        for (int ni = 0; ni < 4; ni++) {
            int c0 = bn * 128 + wn * 32 + ni * 8 + 2 * q;
            if (MODE == 0) {
                float v0 = acc[mi][ni][0] * scale, v1 = acc[mi][ni][1] * scale;
                float v2 = acc[mi][ni][2] * scale, v3 = acc[mi][ni][3] * scale;
                *(float2*)&g_scores[(size_t)r0 * NQ + c0]       = make_float2(v0, v1);
                *(float2*)&g_scores[(size_t)(r0 + 8) * NQ + c0] = make_float2(v2, v3);
                if (bm != bn) {   // symmetric mirror
                    g_scores[(size_t)c0 * NQ + r0]           = v0;
                    g_scores[(size_t)(c0 + 1) * NQ + r0]     = v1;
                    g_scores[(size_t)c0 * NQ + r0 + 8]       = v2;
                    g_scores[(size_t)(c0 + 1) * NQ + r0 + 8] = v3;
                }
            } else {
                // cols [0,128) -> new_mag block, [128,256) -> new_phase block
                size_t base = (c0 < 128) ? 0 : ((size_t)NQ * 128 - 128);
                atomicAdd(&Cout[base + (size_t)r0 * 128 + c0], acc[mi][ni][0]);
                atomicAdd(&Cout[base + (size_t)r0 * 128 + c0 + 1], acc[mi][ni][1]);
                atomicAdd(&Cout[base + (size_t)(r0 + 8) * 128 + c0], acc[mi][ni][2]);
                atomicAdd(&Cout[base + (size_t)(r0 + 8) * 128 + c0 + 1], acc[mi][ni][3]);
            }
        }
    }
}

// ---------------- K3: edge bias MLP + scatter-add onto scores (edge_index is int32) ----
__global__ void bias_kernel(const int* __restrict__ ei, const float* __restrict__ rbf,
                            const float* __restrict__ W1, const float* __restrict__ b1,
                            const float* __restrict__ W2, const float* __restrict__ b2) {
    __shared__ float sW1[EDIM * HID];
    __shared__ float sb1[HID], sW2[HID];
    __shared__ float sb2;
    for (int t = threadIdx.x; t < EDIM * HID; t += blockDim.x) sW1[t] = W1[t];
    if (threadIdx.x < HID) { sb1[threadIdx.x] = b1[threadIdx.x]; sW2[threadIdx.x] = W2[threadIdx.x]; }
    if (threadIdx.x == 0) sb2 = b2[0];
    __syncthreads();

    int e = blockIdx.x * blockDim.x + threadIdx.x;
    if (e >= EQ) return;

    float h[HID];
#pragma unroll
    for (int j = 0; j < HID; j++) h[j] = sb1[j];
    const float* r = rbf + (size_t)e * EDIM;
    for (int k = 0; k < EDIM; k++) {
        float rv = __ldg(&r[k]);
#pragma unroll
        for (int j = 0; j < HID; j++) h[j] = fmaf(rv, sW1[k * HID + j], h[j]);
    }
    float bias = sb2;
#pragma unroll
    for (int j = 0; j < HID; j++) {
        float x = h[j];
        float si = x / (1.f + __expf(-x));   // SiLU
        bias = fmaf(si, sW2[j], bias);
    }
    int i  = ei[e];
    int jn = ei[EQ + e];
    atomicAdd(&g_scores[(size_t)i * NQ + jn], bias);
}

// ---------------- K4: row softmax fp32, emit attn as bf16 hi/lo pair ----------------
__global__ __launch_bounds__(256)
void softmax_kernel() {
    __shared__ __align__(16) float4 srow[NQ / 4];   // 32 KB: whole row resident
    __shared__ float red[8];
    int row = blockIdx.x, tid = threadIdx.x;
    const float4* src = (const float4*)(g_scores + (size_t)row * NQ);

    float m = -1e30f;
    for (int u = tid; u < NQ / 4; u += 256) {
        float4 v = src[u];
        srow[u] = v;
        m = fmaxf(m, fmaxf(fmaxf(v.x, v.y), fmaxf(v.z, v.w)));
    }
#pragma unroll
    for (int o = 16; o; o >>= 1) m = fmaxf(m, __shfl_xor_sync(0xffffffffu, m, o));
    if ((tid & 31) == 0) red[tid >> 5] = m;
    __syncthreads();
    float bm = red[0];
#pragma unroll
    for (int w = 1; w < 8; w++) bm = fmaxf(bm, red[w]);
    __syncthreads();

    float sum = 0.f;
    for (int u = tid; u < NQ / 4; u += 256) {
        float4 v = srow[u];
        v.x = __expf(v.x - bm); v.y = __expf(v.y - bm);
        v.z = __expf(v.z - bm); v.w = __expf(v.w - bm);
        srow[u] = v;
        sum += v.x + v.y + v.z + v.w;
    }
#pragma unroll
    for (int o = 16; o; o >>= 1) sum += __shfl_xor_sync(0xffffffffu, sum, o);
    if ((tid & 31) == 0) red[tid >> 5] = sum;
    __syncthreads();
    float tot = 0.f;
#pragma unroll
    for (int w = 0; w < 8; w++) tot += red[w];
    float inv = 1.f / tot;

    uint2* dhi = (uint2*)(g_attn_hi + (size_t)row * NQ);
    uint2* dlo = (uint2*)(g_attn_lo + (size_t)row * NQ);
    for (int u = tid; u < NQ / 4; u += 256) {
        float4 v = srow[u];
        float p0 = v.x * inv, p1 = v.y * inv, p2 = v.z * inv, p3 = v.w * inv;
        __nv_bfloat16 h0, l0, h1, l1, h2, l2, h3, l3;
        split_bf16(p0, h0, l0); split_bf16(p1, h1, l1);
        split_bf16(p2, h2, l2); split_bf16(p3, h3, l3);
        __nv_bfloat162 hp0 = {h0, h1}, hp1 = {h2, h3};
        __nv_bfloat162 lp0 = {l0, l1}, lp1 = {l2, l3};
        uint2 oh, ol;
        oh.x = *(unsigned*)&hp0; oh.y = *(unsigned*)&hp1;
        ol.x = *(unsigned*)&lp0; ol.y = *(unsigned*)&lp1;
        dhi[u] = oh;
        dlo[u] = ol;
    }
}

// ---------------- K5: zero output (required before atomic split-K epilogue) ----------
__global__ void zero_kernel(float* __restrict__ out) {
    out[(size_t)blockIdx.x * 256 + threadIdx.x] = 0.f;
}

// ---------------- launch ----------------
extern "C" void kernel_launch(void* const* d_in, const int* in_sizes, int n_in,
                              void* d_out, int out_size) {
    const float* mag   = (const float*)d_in[0];
    const float* phase = (const float*)d_in[1];
    const int*   ei    = (const int*)d_in[2];
    const float* rbf   = (const float*)d_in[3];
    const float* W1    = (const float*)d_in[4];
    const float* b1    = (const float*)d_in[5];
    const float* W2    = (const float*)d_in[6];
    const float* b2    = (const float*)d_in[7];
    float*       out   = (float*)d_out;

    const float inv_sqrt_d = 0.08838834764831843f;   // 1/sqrt(128)
    const int smem_bytes = 2 * STAGEB;               // 81920

    cudaFuncSetAttribute(gemm_kernel<0>, cudaFuncAttributeMaxDynamicSharedMemorySize, smem_bytes);
    cudaFuncSetAttribute(gemm_kernel<1>, cudaFuncAttributeMaxDynamicSharedMemorySize, smem_bytes);

    prep_kernel<<<(NQ * DQ) / 256, 256>>>(mag, phase);
    gemm_kernel<0><<<dim3(NQ / 128, NQ / 128), 256, smem_bytes>>>(nullptr, inv_sqrt_d);
    bias_kernel<<<EQ / 256, 256>>>(ei, rbf, W1, b1, W2, b2);
    softmax_kernel<<<NQ, 256>>>();
    zero_kernel<<<(NQ * 256) / 256, 256>>>(out);
    gemm_kernel<1><<<dim3(2, NQ / 128, 2), 256, smem_bytes>>>(out, 1.0f);
}

// round 7
// speedup vs baseline: 1.2480x; 1.2480x over previous
#include <cuda_runtime.h>
#include <cuda_fp16.h>
#include <math.h>
#include <stdint.h>

#define NQ 8192
#define DQ 128
#define EQ 262144
#define EDIM 50
#define HID 32

// ---------------- scratch (device globals: no allocation allowed) ----------------
__device__ float   g_scores [(size_t)NQ * NQ];    // 256 MiB fp32 logits
__device__ __half  g_attn   [(size_t)NQ * NQ];    // 128 MiB fp16 probabilities
__device__ __half  g_ab_hi  [(size_t)NQ * 256];   // [N][a|b], K=256 (fp16 hi)
__device__ __half  g_ab_lo  [(size_t)NQ * 256];   // (fp16 lo)
__device__ __half  g_mpT_hi [(size_t)256 * NQ];   // [mag|phase]^T (fp16 hi)
__device__ __half  g_mpT_lo [(size_t)256 * NQ];   // (fp16 lo)

__device__ __forceinline__ void split_f16(float x, __half& hi, __half& lo) {
    hi = __float2half_rn(x);
    lo = __float2half_rn(x - __half2float(hi));
}

__device__ __forceinline__ void cp_async16(void* sdst, const void* gsrc) {
    unsigned s = (unsigned)__cvta_generic_to_shared(sdst);
    asm volatile("cp.async.cg.shared.global [%0], [%1], 16;\n" :: "r"(s), "l"(gsrc));
}
#define CP_COMMIT() asm volatile("cp.async.commit_group;\n" ::: "memory")
#define CP_WAIT1()  asm volatile("cp.async.wait_group 1;\n" ::: "memory")

// ---------------- K1: prep a,b (fp16 hi/lo) and transposed mag/phase (fp16 hi/lo) -------
__global__ void prep_kernel(const float* __restrict__ mag, const float* __restrict__ phase) {
    int idx = blockIdx.x * blockDim.x + threadIdx.x;   // < N*D
    int i = idx >> 7;
    int d = idx & 127;
    float m = mag[idx];
    float p = phase[idx];
    float s, c;
    __sincosf(p, &s, &c);
    __half h, l;
    split_f16(m * c, h, l);
    g_ab_hi[(size_t)i * 256 + d] = h;  g_ab_lo[(size_t)i * 256 + d] = l;
    split_f16(m * s, h, l);
    g_ab_hi[(size_t)i * 256 + 128 + d] = h;  g_ab_lo[(size_t)i * 256 + 128 + d] = l;
    split_f16(m, h, l);
    g_mpT_hi[(size_t)d * NQ + i] = h;  g_mpT_lo[(size_t)d * NQ + i] = l;
    split_f16(p, h, l);
    g_mpT_hi[(size_t)(128 + d) * NQ + i] = h;  g_mpT_lo[(size_t)(128 + d) * NQ + i] = l;
}

// ---------------- GEMM (fp16, fp32 accum): BM=BN=128, BK=32, 8 warps 2x4, m16n8k16 ------
// cp.async 2-stage double buffer.
// MODE 0 (3 terms: AhBh + AhBl + AlBh): A=B=g_ab, K=256, C=g_scores scaled;
//        SYMMETRIC: bm<=bn tiles only + mirrored store.
// MODE 1 (2 terms: A*Bh + A*Bl): A=g_attn (fp16, exact), B=g_mpT hi/lo,
//        K=8192 split-K z=4, atomicAdd into Cout.
#define TSTRIDE 40
#define TSZ (128 * TSTRIDE)

template <int MODE>
__global__ __launch_bounds__(256)
void gemm_kernel(float* __restrict__ Cout, float scale) {
    extern __shared__ __align__(16) __half dsm[];   // [2 stages][NT tensors][128][40]

    const int NT = (MODE == 0) ? 4 : 3;
    const int bm = blockIdx.y, bn = blockIdx.x;
    if (MODE == 0 && bn < bm) return;   // symmetric: upper-triangle tiles only

    const int K = (MODE == 0) ? 256 : NQ;
    // tensor order MODE0: {Ah, Al, Bh, Bl};  MODE1: {A, Bh, Bl}
    const __half* T0 = (MODE == 0) ? (g_ab_hi + (size_t)bm * 128 * K)
                                   : (g_attn  + (size_t)bm * 128 * K);
    const __half* T1 = (MODE == 0) ? (g_ab_lo + (size_t)bm * 128 * K)
                                   : (g_mpT_hi + (size_t)bn * 128 * K);
    const __half* T2 = (MODE == 0) ? (g_ab_hi + (size_t)bn * 128 * K)
                                   : (g_mpT_lo + (size_t)bn * 128 * K);
    const __half* T3 = (MODE == 0) ? (g_ab_lo + (size_t)bn * 128 * K) : nullptr;

    const int tid = threadIdx.x;
    const int warp = tid >> 5, lane = tid & 31;
    const int wm = warp >> 2, wn = warp & 3;
    const int g = lane >> 2, q = lane & 3;

    float acc[4][4][4];
#pragma unroll
    for (int mi = 0; mi < 4; mi++)
#pragma unroll
        for (int ni = 0; ni < 4; ni++)
#pragma unroll
            for (int r = 0; r < 4; r++) acc[mi][ni][r] = 0.f;

    const int kbeg = (MODE == 0) ? 0 : blockIdx.z * (NQ / 4);
    const int nit = ((MODE == 0) ? 256 : NQ / 4) / 32;

    const int lr = tid >> 2;        // 0..63
    const int lc = (tid & 3) * 8;   // fp16 col of uint4

#define PREFETCH(IT, ST)                                                         \
    do {                                                                         \
        int k0_ = kbeg + (IT) * 32;                                              \
        __half* d_ = dsm + (ST) * NT * TSZ;                                      \
        _Pragma("unroll")                                                        \
        for (int hf = 0; hf < 2; hf++) {                                         \
            int r_ = lr + hf * 64;                                               \
            size_t go_ = (size_t)r_ * K + k0_ + lc;                              \
            int so_ = r_ * TSTRIDE + lc;                                         \
            cp_async16(d_ + 0 * TSZ + so_, T0 + go_);                            \
            cp_async16(d_ + 1 * TSZ + so_, T1 + go_);                            \
            cp_async16(d_ + 2 * TSZ + so_, T2 + go_);                            \
            if (MODE == 0) cp_async16(d_ + 3 * TSZ + so_, T3 + go_);             \
        }                                                                        \
    } while (0)

    PREFETCH(0, 0);
    CP_COMMIT();

    for (int it = 0; it < nit; it++) {
        if (it + 1 < nit) PREFETCH(it + 1, (it + 1) & 1);
        CP_COMMIT();
        CP_WAIT1();
        __syncthreads();

        const __half* s0 = dsm + (it & 1) * NT * TSZ;             // Ah | A
        const __half* s1 = s0 + TSZ;                               // Al | Bh
        const __half* s2 = s0 + 2 * TSZ;                           // Bh | Bl
        const __half* s3 = s0 + 3 * TSZ;                           // Bl | --

#pragma unroll
        for (int kk = 0; kk < 2; kk++) {
            int c0 = kk * 16 + 2 * q;
            unsigned ra0[4][4], ra1[4][4], rb0[4][2], rb1[4][2];
#pragma unroll
            for (int mi = 0; mi < 4; mi++) {
                int r0 = (wm * 64 + mi * 16 + g) * TSTRIDE;
                ra0[mi][0] = *(const unsigned*)&s0[r0 + c0];
                ra0[mi][1] = *(const unsigned*)&s0[r0 + 8 * TSTRIDE + c0];
                ra0[mi][2] = *(const unsigned*)&s0[r0 + c0 + 8];
                ra0[mi][3] = *(const unsigned*)&s0[r0 + 8 * TSTRIDE + c0 + 8];
                if (MODE == 0) {
                    ra1[mi][0] = *(const unsigned*)&s1[r0 + c0];
                    ra1[mi][1] = *(const unsigned*)&s1[r0 + 8 * TSTRIDE + c0];
                    ra1[mi][2] = *(const unsigned*)&s1[r0 + c0 + 8];
                    ra1[mi][3] = *(const unsigned*)&s1[r0 + 8 * TSTRIDE + c0 + 8];
                }
            }
            const __half* Bh = (MODE == 0) ? s2 : s1;
            const __half* Bl = (MODE == 0) ? s3 : s2;
#pragma unroll
            for (int ni = 0; ni < 4; ni++) {
                int r0 = (wn * 32 + ni * 8 + g) * TSTRIDE;
                rb0[ni][0] = *(const unsigned*)&Bh[r0 + c0];
                rb0[ni][1] = *(const unsigned*)&Bh[r0 + c0 + 8];
                rb1[ni][0] = *(const unsigned*)&Bl[r0 + c0];
                rb1[ni][1] = *(const unsigned*)&Bl[r0 + c0 + 8];
            }
#define MMA(AA, BB)                                                                \
    asm volatile(                                                                  \
        "mma.sync.aligned.m16n8k16.row.col.f32.f16.f16.f32 "                       \
        "{%0,%1,%2,%3}, {%4,%5,%6,%7}, {%8,%9}, {%0,%1,%2,%3};\n"                  \
        : "+f"(acc[mi][ni][0]), "+f"(acc[mi][ni][1]),                              \
          "+f"(acc[mi][ni][2]), "+f"(acc[mi][ni][3])                               \
        : "r"(AA[mi][0]), "r"(AA[mi][1]), "r"(AA[mi][2]), "r"(AA[mi][3]),          \
          "r"(BB[ni][0]), "r"(BB[ni][1]))
#pragma unroll
            for (int mi = 0; mi < 4; mi++)
#pragma unroll
                for (int ni = 0; ni < 4; ni++) {
                    MMA(ra0, rb0);            // Ah*Bh | A*Bh
                    MMA(ra0, rb1);            // Ah*Bl | A*Bl
                    if (MODE == 0) MMA(ra1, rb0);   // Al*Bh
                }
#undef MMA
        }
        __syncthreads();
    }
#undef PREFETCH

    // epilogue
#pragma unroll
    for (int mi = 0; mi < 4; mi++) {
        int r0 = bm * 128 + wm * 64 + mi * 16 + g;
#pragma unroll
        for (int ni = 0; ni < 4; ni++) {
            int c0 = bn * 128 + wn * 32 + ni * 8 + 2 * q;
            if (MODE == 0) {
                float v0 = acc[mi][ni][0] * scale, v1 = acc[mi][ni][1] * scale;
                float v2 = acc[mi][ni][2] * scale, v3 = acc[mi][ni][3] * scale;
                *(float2*)&g_scores[(size_t)r0 * NQ + c0]       = make_float2(v0, v1);
                *(float2*)&g_scores[(size_t)(r0 + 8) * NQ + c0] = make_float2(v2, v3);
                if (bm != bn) {   // symmetric mirror
                    g_scores[(size_t)c0 * NQ + r0]           = v0;
                    g_scores[(size_t)(c0 + 1) * NQ + r0]     = v1;
                    g_scores[(size_t)c0 * NQ + r0 + 8]       = v2;
                    g_scores[(size_t)(c0 + 1) * NQ + r0 + 8] = v3;
                }
            } else {
                // cols [0,128) -> new_mag block, [128,256) -> new_phase block
                size_t base = (c0 < 128) ? 0 : ((size_t)NQ * 128 - 128);
                atomicAdd(&Cout[base + (size_t)r0 * 128 + c0], acc[mi][ni][0]);
                atomicAdd(&Cout[base + (size_t)r0 * 128 + c0 + 1], acc[mi][ni][1]);
                atomicAdd(&Cout[base + (size_t)(r0 + 8) * 128 + c0], acc[mi][ni][2]);
                atomicAdd(&Cout[base + (size_t)(r0 + 8) * 128 + c0 + 1], acc[mi][ni][3]);
            }
        }
    }
}

// ---------------- K3: edge bias MLP + scatter-add onto scores (edge_index is int32) ----
__global__ void bias_kernel(const int* __restrict__ ei, const float* __restrict__ rbf,
                            const float* __restrict__ W1, const float* __restrict__ b1,
                            const float* __restrict__ W2, const float* __restrict__ b2) {
    __shared__ float sW1[EDIM * HID];
    __shared__ float sb1[HID], sW2[HID];
    __shared__ float sb2;
    for (int t = threadIdx.x; t < EDIM * HID; t += blockDim.x) sW1[t] = W1[t];
    if (threadIdx.x < HID) { sb1[threadIdx.x] = b1[threadIdx.x]; sW2[threadIdx.x] = W2[threadIdx.x]; }
    if (threadIdx.x == 0) sb2 = b2[0];
    __syncthreads();

    int e = blockIdx.x * blockDim.x + threadIdx.x;
    if (e >= EQ) return;

    float h[HID];
#pragma unroll
    for (int j = 0; j < HID; j++) h[j] = sb1[j];
    const float* r = rbf + (size_t)e * EDIM;
    for (int k = 0; k < EDIM; k++) {
        float rv = __ldg(&r[k]);
#pragma unroll
        for (int j = 0; j < HID; j++) h[j] = fmaf(rv, sW1[k * HID + j], h[j]);
    }
    float bias = sb2;
#pragma unroll
    for (int j = 0; j < HID; j++) {
        float x = h[j];
        float si = x / (1.f + __expf(-x));   // SiLU
        bias = fmaf(si, sW2[j], bias);
    }
    int i  = ei[e];
    int jn = ei[EQ + e];
    atomicAdd(&g_scores[(size_t)i * NQ + jn], bias);
}

// ---------------- K4: row softmax fp32, emit attn as fp16 ----------------
__global__ __launch_bounds__(256)
void softmax_kernel() {
    __shared__ __align__(16) float4 srow[NQ / 4];   // 32 KB: whole row resident
    __shared__ float red[8];
    int row = blockIdx.x, tid = threadIdx.x;
    const float4* src = (const float4*)(g_scores + (size_t)row * NQ);

    float m = -1e30f;
    for (int u = tid; u < NQ / 4; u += 256) {
        float4 v = src[u];
        srow[u] = v;
        m = fmaxf(m, fmaxf(fmaxf(v.x, v.y), fmaxf(v.z, v.w)));
    }
#pragma unroll
    for (int o = 16; o; o >>= 1) m = fmaxf(m, __shfl_xor_sync(0xffffffffu, m, o));
    if ((tid & 31) == 0) red[tid >> 5] = m;
    __syncthreads();
    float bm = red[0];
#pragma unroll
    for (int w = 1; w < 8; w++) bm = fmaxf(bm, red[w]);
    __syncthreads();

    float sum = 0.f;
    for (int u = tid; u < NQ / 4; u += 256) {
        float4 v = srow[u];
        v.x = __expf(v.x - bm); v.y = __expf(v.y - bm);
        v.z = __expf(v.z - bm); v.w = __expf(v.w - bm);
        srow[u] = v;
        sum += v.x + v.y + v.z + v.w;
    }
#pragma unroll
    for (int o = 16; o; o >>= 1) sum += __shfl_xor_sync(0xffffffffu, sum, o);
    if ((tid & 31) == 0) red[tid >> 5] = sum;
    __syncthreads();
    float tot = 0.f;
#pragma unroll
    for (int w = 0; w < 8; w++) tot += red[w];
    float inv = 1.f / tot;

    uint2* dst = (uint2*)(g_attn + (size_t)row * NQ);
    for (int u = tid; u < NQ / 4; u += 256) {
        float4 v = srow[u];
        __half2 lo = __floats2half2_rn(v.x * inv, v.y * inv);
        __half2 hi = __floats2half2_rn(v.z * inv, v.w * inv);
        uint2 o;
        o.x = *(unsigned*)&lo;
        o.y = *(unsigned*)&hi;
        dst[u] = o;
    }
}

// ---------------- K5: zero output (required before atomic split-K epilogue) ----------
__global__ void zero_kernel(float* __restrict__ out) {
    out[(size_t)blockIdx.x * 256 + threadIdx.x] = 0.f;
}

// ---------------- launch ----------------
extern "C" void kernel_launch(void* const* d_in, const int* in_sizes, int n_in,
                              void* d_out, int out_size) {
    const float* mag   = (const float*)d_in[0];
    const float* phase = (const float*)d_in[1];
    const int*   ei    = (const int*)d_in[2];
    const float* rbf   = (const float*)d_in[3];
    const float* W1    = (const float*)d_in[4];
    const float* b1    = (const float*)d_in[5];
    const float* W2    = (const float*)d_in[6];
    const float* b2    = (const float*)d_in[7];
    float*       out   = (float*)d_out;

    const float inv_sqrt_d = 0.08838834764831843f;   // 1/sqrt(128)
    const int smem0 = 2 * 4 * TSZ * (int)sizeof(__half);   // 81920
    const int smem1 = 2 * 3 * TSZ * (int)sizeof(__half);   // 61440

    cudaFuncSetAttribute(gemm_kernel<0>, cudaFuncAttributeMaxDynamicSharedMemorySize, smem0);
    cudaFuncSetAttribute(gemm_kernel<1>, cudaFuncAttributeMaxDynamicSharedMemorySize, smem1);

    prep_kernel<<<(NQ * DQ) / 256, 256>>>(mag, phase);
    gemm_kernel<0><<<dim3(NQ / 128, NQ / 128), 256, smem0>>>(nullptr, inv_sqrt_d);
    bias_kernel<<<EQ / 256, 256>>>(ei, rbf, W1, b1, W2, b2);
    softmax_kernel<<<NQ, 256>>>();
    zero_kernel<<<(NQ * 256) / 256, 256>>>(out);
    gemm_kernel<1><<<dim3(2, NQ / 128, 4), 256, smem1>>>(out, 1.0f);
}

// round 9
// speedup vs baseline: 1.3921x; 1.1155x over previous
#include <cuda_runtime.h>
#include <cuda_fp16.h>
#include <math.h>
#include <stdint.h>

#define NQ 8192
#define DQ 128
#define EQ 262144
#define EDIM 50
#define HID 32

// ---------------- scratch (device globals: no allocation allowed) ----------------
__device__ float   g_scores [(size_t)NQ * NQ];    // 256 MiB fp32 logits
__device__ __half  g_attn   [(size_t)NQ * NQ];    // 128 MiB fp16 probabilities
__device__ __half  g_ab_hi  [(size_t)NQ * 256];   // [N][a|b], K=256 (fp16 hi)
__device__ __half  g_ab_lo  [(size_t)NQ * 256];   // (fp16 lo)
__device__ __half  g_mpT_hi [(size_t)256 * NQ];   // [mag|phase]^T (fp16 hi)
__device__ __half  g_mpT_lo [(size_t)256 * NQ];   // (fp16 lo)

__device__ __forceinline__ void split_f16(float x, __half& hi, __half& lo) {
    hi = __float2half_rn(x);
    lo = __float2half_rn(x - __half2float(hi));
}

__device__ __forceinline__ uint32_t smem_u32(const void* p) {
    uint32_t a;
    asm("{ .reg .u64 t; cvta.to.shared.u64 t, %1; cvt.u32.u64 %0, t; }" : "=r"(a) : "l"(p));
    return a;
}
__device__ __forceinline__ void cp_async16(void* sdst, const void* gsrc) {
    unsigned s = (unsigned)__cvta_generic_to_shared(sdst);
    asm volatile("cp.async.cg.shared.global [%0], [%1], 16;\n" :: "r"(s), "l"(gsrc));
}
#define CP_COMMIT() asm volatile("cp.async.commit_group;\n" ::: "memory")
#define CP_WAIT1()  asm volatile("cp.async.wait_group 1;\n" ::: "memory")

__device__ __forceinline__ void ldmx4(uint32_t* r, uint32_t addr) {
    asm volatile("ldmatrix.sync.aligned.m8n8.x4.shared.b16 {%0,%1,%2,%3}, [%4];"
                 : "=r"(r[0]), "=r"(r[1]), "=r"(r[2]), "=r"(r[3]) : "r"(addr));
}

// ---------------- K1: prep a,b (fp16 hi/lo) and transposed mag/phase (fp16 hi/lo) -------
__global__ void prep_kernel(const float* __restrict__ mag, const float* __restrict__ phase) {
    int idx = blockIdx.x * blockDim.x + threadIdx.x;   // < N*D
    int i = idx >> 7;
    int d = idx & 127;
    float m = mag[idx];
    float p = phase[idx];
    float s, c;
    __sincosf(p, &s, &c);
    __half h, l;
    split_f16(m * c, h, l);
    g_ab_hi[(size_t)i * 256 + d] = h;  g_ab_lo[(size_t)i * 256 + d] = l;
    split_f16(m * s, h, l);
    g_ab_hi[(size_t)i * 256 + 128 + d] = h;  g_ab_lo[(size_t)i * 256 + 128 + d] = l;
    split_f16(m, h, l);
    g_mpT_hi[(size_t)d * NQ + i] = h;  g_mpT_lo[(size_t)d * NQ + i] = l;
    split_f16(p, h, l);
    g_mpT_hi[(size_t)(128 + d) * NQ + i] = h;  g_mpT_lo[(size_t)(128 + d) * NQ + i] = l;
}

// ---------------- GEMM (fp16, fp32 accum): BM=BN=128, BK=32, 8 warps 2x4, m16n8k16 ------
// 3 smem tensors, 2 MMA terms, cp.async double buffer, ldmatrix.x4 fragments.
// MODE 0: T={Ah[bm], Al[bm], Bh[bn]}, C += (Ah+Al)*Bh^T; K=256, scores scaled;
//         SYMMETRIC: bm<=bn tiles only + mirrored store.
// MODE 1: T={A[bm](attn fp16), Bh[bn], Bl[bn]}, C += A*(Bh+Bl)^T; K=8192 split-K z=4.
#define TSTRIDE 40
#define TSZ (128 * TSTRIDE)
#define TSZB (TSZ * 2)

template <int MODE>
__global__ __launch_bounds__(256)
void gemm_kernel(float* __restrict__ Cout, float scale) {
    extern __shared__ __align__(16) __half dsm[];   // [2 stages][3 tensors][128][40]

    const int bm = blockIdx.y, bn = blockIdx.x;
    if (MODE == 0 && bn < bm) return;   // symmetric: upper-triangle tiles only

    const int K = (MODE == 0) ? 256 : NQ;
    const __half* T0 = (MODE == 0) ? (g_ab_hi + (size_t)bm * 128 * K)
                                   : (g_attn  + (size_t)bm * 128 * K);
    const __half* T1 = (MODE == 0) ? (g_ab_lo + (size_t)bm * 128 * K)
                                   : (g_mpT_hi + (size_t)bn * 128 * K);
    const __half* T2 = (MODE == 0) ? (g_ab_hi + (size_t)bn * 128 * K)
                                   : (g_mpT_lo + (size_t)bn * 128 * K);

    const int tid = threadIdx.x;
    const int warp = tid >> 5, lane = tid & 31;
    const int wm = warp >> 2, wn = warp & 3;
    const int g = lane >> 2, q = lane & 3;

    float acc[4][4][4];
#pragma unroll
    for (int mi = 0; mi < 4; mi++)
#pragma unroll
        for (int ni = 0; ni < 4; ni++)
#pragma unroll
            for (int r = 0; r < 4; r++) acc[mi][ni][r] = 0.f;

    const int kbeg = (MODE == 0) ? 0 : blockIdx.z * (NQ / 4);
    const int nit = ((MODE == 0) ? 256 : NQ / 4) / 32;

    const int lr = tid >> 2;        // 0..63
    const int lc = (tid & 3) * 8;   // fp16 col of uint4

    // ldmatrix per-lane byte offsets (row stride 80 B; banks conflict-free)
    const int xr = lane & 7;
    const int xb = (lane >> 3) & 1;
    const int xk = (lane >> 4) & 1;
    uint32_t aoff[4], boff[2];
#pragma unroll
    for (int mi = 0; mi < 4; mi++)
        aoff[mi] = (uint32_t)((wm * 64 + mi * 16 + xb * 8 + xr) * (TSTRIDE * 2) + xk * 16);
#pragma unroll
    for (int pi = 0; pi < 2; pi++)
        boff[pi] = (uint32_t)((wn * 32 + pi * 16 + xb * 8 + xr) * (TSTRIDE * 2) + xk * 16);

    const uint32_t smbase = smem_u32(dsm);

#define PREFETCH(IT, ST)                                                         \
    do {                                                                         \
        int k0_ = kbeg + (IT) * 32;                                              \
        __half* d_ = dsm + (ST) * 3 * TSZ;                                       \
        _Pragma("unroll")                                                        \
        for (int hf = 0; hf < 2; hf++) {                                         \
            int r_ = lr + hf * 64;                                               \
            size_t go_ = (size_t)r_ * K + k0_ + lc;                              \
            int so_ = r_ * TSTRIDE + lc;                                         \
            cp_async16(d_ + 0 * TSZ + so_, T0 + go_);                            \
            cp_async16(d_ + 1 * TSZ + so_, T1 + go_);                            \
            cp_async16(d_ + 2 * TSZ + so_, T2 + go_);                            \
        }                                                                        \
    } while (0)

    PREFETCH(0, 0);
    CP_COMMIT();

    for (int it = 0; it < nit; it++) {
        if (it + 1 < nit) PREFETCH(it + 1, (it + 1) & 1);
        CP_COMMIT();
        CP_WAIT1();
        __syncthreads();

        const uint32_t S0 = smbase + (uint32_t)(it & 1) * 3 * TSZB;
        const uint32_t S1 = S0 + TSZB;
        const uint32_t S2 = S0 + 2 * TSZB;

#pragma unroll
        for (int kk = 0; kk < 2; kk++) {
            const uint32_t kb = kk * 32;
            uint32_t ra0[4][4], ra1[4][4], rb0[2][4], rb1[2][4];
            if (MODE == 0) {
                // A-frags from Ah(S0), Al(S1); B-frags from Bh(S2)
#pragma unroll
                for (int mi = 0; mi < 4; mi++) {
                    ldmx4(ra0[mi], S0 + aoff[mi] + kb);
                    ldmx4(ra1[mi], S1 + aoff[mi] + kb);
                }
#pragma unroll
                for (int pi = 0; pi < 2; pi++) ldmx4(rb0[pi], S2 + boff[pi] + kb);
            } else {
                // A-frags from A(S0); B-frags from Bh(S1), Bl(S2)
#pragma unroll
                for (int mi = 0; mi < 4; mi++) ldmx4(ra0[mi], S0 + aoff[mi] + kb);
#pragma unroll
                for (int pi = 0; pi < 2; pi++) {
                    ldmx4(rb0[pi], S1 + boff[pi] + kb);
                    ldmx4(rb1[pi], S2 + boff[pi] + kb);
                }
            }
#define MMA4(AC, AA, B0, B1)                                                       \
    asm volatile(                                                                  \
        "mma.sync.aligned.m16n8k16.row.col.f32.f16.f16.f32 "                       \
        "{%0,%1,%2,%3}, {%4,%5,%6,%7}, {%8,%9}, {%0,%1,%2,%3};\n"                  \
        : "+f"((AC)[0]), "+f"((AC)[1]), "+f"((AC)[2]), "+f"((AC)[3])               \
        : "r"((AA)[0]), "r"((AA)[1]), "r"((AA)[2]), "r"((AA)[3]),                  \
          "r"(B0), "r"(B1))
#pragma unroll
            for (int mi = 0; mi < 4; mi++)
#pragma unroll
                for (int ni = 0; ni < 4; ni++) {
                    const int pi = ni >> 1, h = ni & 1;
                    if (MODE == 0) {
                        MMA4(acc[mi][ni], ra0[mi], rb0[pi][h], rb0[pi][h + 2]);
                        MMA4(acc[mi][ni], ra1[mi], rb0[pi][h], rb0[pi][h + 2]);
                    } else {
                        MMA4(acc[mi][ni], ra0[mi], rb0[pi][h], rb0[pi][h + 2]);
                        MMA4(acc[mi][ni], ra0[mi], rb1[pi][h], rb1[pi][h + 2]);
                    }
                }
#undef MMA4
        }
        __syncthreads();
    }
#undef PREFETCH

    // epilogue
#pragma unroll
    for (int mi = 0; mi < 4; mi++) {
        int r0 = bm * 128 + wm * 64 + mi * 16 + g;
#pragma unroll
        for (int ni = 0; ni < 4; ni++) {
            int c0 = bn * 128 + wn * 32 + ni * 8 + 2 * q;
            if (MODE == 0) {
                float v0 = acc[mi][ni][0] * scale, v1 = acc[mi][ni][1] * scale;
                float v2 = acc[mi][ni][2] * scale, v3 = acc[mi][ni][3] * scale;
                *(float2*)&g_scores[(size_t)r0 * NQ + c0]       = make_float2(v0, v1);
                *(float2*)&g_scores[(size_t)(r0 + 8) * NQ + c0] = make_float2(v2, v3);
                if (bm != bn) {   // symmetric mirror
                    g_scores[(size_t)c0 * NQ + r0]           = v0;
                    g_scores[(size_t)(c0 + 1) * NQ + r0]     = v1;
                    g_scores[(size_t)c0 * NQ + r0 + 8]       = v2;
                    g_scores[(size_t)(c0 + 1) * NQ + r0 + 8] = v3;
                }
            } else {
                size_t base = (c0 < 128) ? 0 : ((size_t)NQ * 128 - 128);
                atomicAdd(&Cout[base + (size_t)r0 * 128 + c0], acc[mi][ni][0]);
                atomicAdd(&Cout[base + (size_t)r0 * 128 + c0 + 1], acc[mi][ni][1]);
                atomicAdd(&Cout[base + (size_t)(r0 + 8) * 128 + c0], acc[mi][ni][2]);
                atomicAdd(&Cout[base + (size_t)(r0 + 8) * 128 + c0 + 1], acc[mi][ni][3]);
            }
        }
    }
}

// ---------------- K3: edge bias MLP + scatter-add onto scores (edge_index is int32) ----
__global__ void bias_kernel(const int* __restrict__ ei, const float* __restrict__ rbf,
                            const float* __restrict__ W1, const float* __restrict__ b1,
                            const float* __restrict__ W2, const float* __restrict__ b2) {
    __shared__ float sW1[EDIM * HID];
    __shared__ float sb1[HID], sW2[HID];
    __shared__ float sb2;
    for (int t = threadIdx.x; t < EDIM * HID; t += blockDim.x) sW1[t] = W1[t];
    if (threadIdx.x < HID) { sb1[threadIdx.x] = b1[threadIdx.x]; sW2[threadIdx.x] = W2[threadIdx.x]; }
    if (threadIdx.x == 0) sb2 = b2[0];
    __syncthreads();

    int e = blockIdx.x * blockDim.x + threadIdx.x;
    if (e >= EQ) return;

    float h[HID];
#pragma unroll
    for (int j = 0; j < HID; j++) h[j] = sb1[j];
    const float* r = rbf + (size_t)e * EDIM;
    for (int k = 0; k < EDIM; k++) {
        float rv = __ldg(&r[k]);
#pragma unroll
        for (int j = 0; j < HID; j++) h[j] = fmaf(rv, sW1[k * HID + j], h[j]);
    }
    float bias = sb2;
#pragma unroll
    for (int j = 0; j < HID; j++) {
        float x = h[j];
        float si = x / (1.f + __expf(-x));   // SiLU
        bias = fmaf(si, sW2[j], bias);
    }
    int i  = ei[e];
    int jn = ei[EQ + e];
    atomicAdd(&g_scores[(size_t)i * NQ + jn], bias);
}

// ---------------- K4: row softmax, register-resident (no smem row buffer) ----------------
__global__ __launch_bounds__(256)
void softmax_kernel() {
    __shared__ float red[8];
    const int row = blockIdx.x, tid = threadIdx.x;
    const float4* src = (const float4*)(g_scores + (size_t)row * NQ);

    float4 v[8];
    float m = -1e30f;
#pragma unroll
    for (int i = 0; i < 8; i++) {
        v[i] = src[tid + i * 256];
        m = fmaxf(m, fmaxf(fmaxf(v[i].x, v[i].y), fmaxf(v[i].z, v[i].w)));
    }
#pragma unroll
    for (int o = 16; o; o >>= 1) m = fmaxf(m, __shfl_xor_sync(0xffffffffu, m, o));
    if ((tid & 31) == 0) red[tid >> 5] = m;
    __syncthreads();
    float bm = red[0];
#pragma unroll
    for (int w = 1; w < 8; w++) bm = fmaxf(bm, red[w]);
    __syncthreads();

    float sum = 0.f;
#pragma unroll
    for (int i = 0; i < 8; i++) {
        v[i].x = __expf(v[i].x - bm); v[i].y = __expf(v[i].y - bm);
        v[i].z = __expf(v[i].z - bm); v[i].w = __expf(v[i].w - bm);
        sum += v[i].x + v[i].y + v[i].z + v[i].w;
    }
#pragma unroll
    for (int o = 16; o; o >>= 1) sum += __shfl_xor_sync(0xffffffffu, sum, o);
    if ((tid & 31) == 0) red[tid >> 5] = sum;
    __syncthreads();
    float tot = 0.f;
#pragma unroll
    for (int w = 0; w < 8; w++) tot += red[w];
    const float inv = 1.f / tot;

    uint2* dst = (uint2*)(g_attn + (size_t)row * NQ);
#pragma unroll
    for (int i = 0; i < 8; i++) {
        __half2 lo = __floats2half2_rn(v[i].x * inv, v[i].y * inv);
        __half2 hi = __floats2half2_rn(v[i].z * inv, v[i].w * inv);
        uint2 o;
        o.x = *(unsigned*)&lo;
        o.y = *(unsigned*)&hi;
        dst[tid + i * 256] = o;
    }
}

// ---------------- K5: zero output (required before atomic split-K epilogue) ----------
__global__ void zero_kernel(float* __restrict__ out) {
    out[(size_t)blockIdx.x * 256 + threadIdx.x] = 0.f;
}

// ---------------- launch ----------------
extern "C" void kernel_launch(void* const* d_in, const int* in_sizes, int n_in,
                              void* d_out, int out_size) {
    const float* mag   = (const float*)d_in[0];
    const float* phase = (const float*)d_in[1];
    const int*   ei    = (const int*)d_in[2];
    const float* rbf   = (const float*)d_in[3];
    const float* W1    = (const float*)d_in[4];
    const float* b1    = (const float*)d_in[5];
    const float* W2    = (const float*)d_in[6];
    const float* b2    = (const float*)d_in[7];
    float*       out   = (float*)d_out;

    const float inv_sqrt_d = 0.08838834764831843f;   // 1/sqrt(128)
    const int smem_bytes = 2 * 3 * TSZ * (int)sizeof(__half);   // 61440

    cudaFuncSetAttribute(gemm_kernel<0>, cudaFuncAttributeMaxDynamicSharedMemorySize, smem_bytes);
    cudaFuncSetAttribute(gemm_kernel<1>, cudaFuncAttributeMaxDynamicSharedMemorySize, smem_bytes);

    prep_kernel<<<(NQ * DQ) / 256, 256>>>(mag, phase);
    gemm_kernel<0><<<dim3(NQ / 128, NQ / 128), 256, smem_bytes>>>(nullptr, inv_sqrt_d);
    bias_kernel<<<EQ / 256, 256>>>(ei, rbf, W1, b1, W2, b2);
    softmax_kernel<<<NQ, 256>>>();
    zero_kernel<<<(NQ * 256) / 256, 256>>>(out);
    gemm_kernel<1><<<dim3(2, NQ / 128, 4), 256, smem_bytes>>>(out, 1.0f);
}

// round 10
// speedup vs baseline: 1.8404x; 1.3220x over previous
#include <cuda_runtime.h>
#include <cuda_fp16.h>
#include <math.h>
#include <stdint.h>

#define NQ 8192
#define DQ 128
#define EQ 262144
#define EDIM 50
#define HID 32

// ---------------- scratch (device globals: no allocation allowed) ----------------
__device__ float   g_scores [(size_t)NQ * NQ];    // 256 MiB fp32 logits
__device__ __half  g_attn   [(size_t)NQ * NQ];    // 128 MiB fp16 probabilities
__device__ __half  g_ab_hi  [(size_t)NQ * 256];   // [N][a|b], K=256 (fp16 hi)
__device__ __half  g_ab_lo  [(size_t)NQ * 256];   // (fp16 lo)
__device__ __half  g_mpT_hi [(size_t)256 * NQ];   // [mag|phase]^T (fp16)

__device__ __forceinline__ void split_f16(float x, __half& hi, __half& lo) {
    hi = __float2half_rn(x);
    lo = __float2half_rn(x - __half2float(hi));
}

__device__ __forceinline__ uint32_t smem_u32(const void* p) {
    uint32_t a;
    asm("{ .reg .u64 t; cvta.to.shared.u64 t, %1; cvt.u32.u64 %0, t; }" : "=r"(a) : "l"(p));
    return a;
}
__device__ __forceinline__ void cp_async16(void* sdst, const void* gsrc) {
    unsigned s = (unsigned)__cvta_generic_to_shared(sdst);
    asm volatile("cp.async.cg.shared.global [%0], [%1], 16;\n" :: "r"(s), "l"(gsrc));
}
#define CP_COMMIT() asm volatile("cp.async.commit_group;\n" ::: "memory")
#define CP_WAIT1()  asm volatile("cp.async.wait_group 1;\n" ::: "memory")

__device__ __forceinline__ void ldmx4(uint32_t* r, uint32_t addr) {
    asm volatile("ldmatrix.sync.aligned.m8n8.x4.shared.b16 {%0,%1,%2,%3}, [%4];"
                 : "=r"(r[0]), "=r"(r[1]), "=r"(r[2]), "=r"(r[3]) : "r"(addr));
}

// ---------------- K1: prep a,b (fp16 hi/lo) and transposed mag/phase (fp16) -------
__global__ void prep_kernel(const float* __restrict__ mag, const float* __restrict__ phase) {
    int idx = blockIdx.x * blockDim.x + threadIdx.x;   // < N*D
    int i = idx >> 7;
    int d = idx & 127;
    float m = mag[idx];
    float p = phase[idx];
    float s, c;
    __sincosf(p, &s, &c);
    __half h, l;
    split_f16(m * c, h, l);
    g_ab_hi[(size_t)i * 256 + d] = h;  g_ab_lo[(size_t)i * 256 + d] = l;
    split_f16(m * s, h, l);
    g_ab_hi[(size_t)i * 256 + 128 + d] = h;  g_ab_lo[(size_t)i * 256 + 128 + d] = l;
    g_mpT_hi[(size_t)d * NQ + i]         = __float2half_rn(m);
    g_mpT_hi[(size_t)(128 + d) * NQ + i] = __float2half_rn(p);
}

// ---------------- GEMM (fp16, fp32 accum): BM=BN=128, BK=64, 8 warps 2x4, m16n8k16 ------
// cp.async double buffer, ldmatrix.x4 fragments.
// MODE 0: T={Ah[bm], Al[bm], Bh[bn]}, C += (Ah+Al)*Bh^T; K=256, scores scaled;
//         SYMMETRIC: bm<=bn tiles only + mirrored store.
// MODE 1: T={A[bm](attn fp16), Bh[bn]}, C += A*Bh^T; K=8192 split-K z=4, atomicAdd.
#define TSTRIDE 72
#define TSZ (128 * TSTRIDE)
#define TSZB (TSZ * 2)

template <int MODE>
__global__ __launch_bounds__(256)
void gemm_kernel(float* __restrict__ Cout, float scale) {
    extern __shared__ __align__(16) __half dsm[];   // [2 stages][NT tensors][128][72]

    const int NT = (MODE == 0) ? 3 : 2;
    const int bm = blockIdx.y, bn = blockIdx.x;
    if (MODE == 0 && bn < bm) return;   // symmetric: upper-triangle tiles only

    const int K = (MODE == 0) ? 256 : NQ;
    const __half* T0 = (MODE == 0) ? (g_ab_hi + (size_t)bm * 128 * K)
                                   : (g_attn  + (size_t)bm * 128 * K);
    const __half* T1 = (MODE == 0) ? (g_ab_lo + (size_t)bm * 128 * K)
                                   : (g_mpT_hi + (size_t)bn * 128 * K);
    const __half* T2 = (MODE == 0) ? (g_ab_hi + (size_t)bn * 128 * K) : nullptr;

    const int tid = threadIdx.x;
    const int warp = tid >> 5, lane = tid & 31;
    const int wm = warp >> 2, wn = warp & 3;
    const int g = lane >> 2, q = lane & 3;

    float acc[4][4][4];
#pragma unroll
    for (int mi = 0; mi < 4; mi++)
#pragma unroll
        for (int ni = 0; ni < 4; ni++)
#pragma unroll
            for (int r = 0; r < 4; r++) acc[mi][ni][r] = 0.f;

    const int kbeg = (MODE == 0) ? 0 : blockIdx.z * (NQ / 4);
    const int nit = ((MODE == 0) ? 256 : NQ / 4) / 64;

    // ldmatrix per-lane byte offsets (row stride 144 B; 8 rows hit distinct bank groups)
    const int xr = lane & 7;
    const int xb = (lane >> 3) & 1;
    const int xk = (lane >> 4) & 1;
    uint32_t aoff[4], boff[2];
#pragma unroll
    for (int mi = 0; mi < 4; mi++)
        aoff[mi] = (uint32_t)((wm * 64 + mi * 16 + xb * 8 + xr) * (TSTRIDE * 2) + xk * 16);
#pragma unroll
    for (int pi = 0; pi < 2; pi++)
        boff[pi] = (uint32_t)((wn * 32 + pi * 16 + xb * 8 + xr) * (TSTRIDE * 2) + xk * 16);

    const uint32_t smbase = smem_u32(dsm);

    // Fill one stage: per tensor 128 rows x 8 chunks(16B) = 1024 units; 4 per thread.
#define PREFETCH(IT, ST)                                                         \
    do {                                                                         \
        int k0_ = kbeg + (IT) * 64;                                              \
        __half* d_ = dsm + (ST) * NT * TSZ;                                      \
        _Pragma("unroll")                                                        \
        for (int i_ = 0; i_ < 4; i_++) {                                         \
            int u_ = tid + i_ * 256;                                             \
            int r_ = u_ >> 3, c_ = (u_ & 7) * 8;                                 \
            size_t go_ = (size_t)r_ * K + k0_ + c_;                              \
            int so_ = r_ * TSTRIDE + c_;                                         \
            cp_async16(d_ + 0 * TSZ + so_, T0 + go_);                            \
            cp_async16(d_ + 1 * TSZ + so_, T1 + go_);                            \
            if (MODE == 0) cp_async16(d_ + 2 * TSZ + so_, T2 + go_);             \
        }                                                                        \
    } while (0)

    PREFETCH(0, 0);
    CP_COMMIT();

    for (int it = 0; it < nit; it++) {
        if (it + 1 < nit) PREFETCH(it + 1, (it + 1) & 1);
        CP_COMMIT();
        CP_WAIT1();
        __syncthreads();

        const uint32_t S0 = smbase + (uint32_t)(it & 1) * NT * TSZB;
        const uint32_t S1 = S0 + TSZB;
        const uint32_t S2 = S0 + 2 * TSZB;

#pragma unroll
        for (int kk = 0; kk < 4; kk++) {
            const uint32_t kb = kk * 32;
            uint32_t ra0[4][4], ra1[4][4], rb0[2][4];
#pragma unroll
            for (int mi = 0; mi < 4; mi++) {
                ldmx4(ra0[mi], S0 + aoff[mi] + kb);
                if (MODE == 0) ldmx4(ra1[mi], S1 + aoff[mi] + kb);
            }
            const uint32_t SB = (MODE == 0) ? S2 : S1;
#pragma unroll
            for (int pi = 0; pi < 2; pi++) ldmx4(rb0[pi], SB + boff[pi] + kb);

#define MMA4(AC, AA, B0, B1)                                                       \
    asm volatile(                                                                  \
        "mma.sync.aligned.m16n8k16.row.col.f32.f16.f16.f32 "                       \
        "{%0,%1,%2,%3}, {%4,%5,%6,%7}, {%8,%9}, {%0,%1,%2,%3};\n"                  \
        : "+f"((AC)[0]), "+f"((AC)[1]), "+f"((AC)[2]), "+f"((AC)[3])               \
        : "r"((AA)[0]), "r"((AA)[1]), "r"((AA)[2]), "r"((AA)[3]),                  \
          "r"(B0), "r"(B1))
#pragma unroll
            for (int mi = 0; mi < 4; mi++)
#pragma unroll
                for (int ni = 0; ni < 4; ni++) {
                    const int pi = ni >> 1, h = ni & 1;
                    MMA4(acc[mi][ni], ra0[mi], rb0[pi][h], rb0[pi][h + 2]);
                    if (MODE == 0)
                        MMA4(acc[mi][ni], ra1[mi], rb0[pi][h], rb0[pi][h + 2]);
                }
#undef MMA4
        }
        __syncthreads();
    }
#undef PREFETCH

    // epilogue
#pragma unroll
    for (int mi = 0; mi < 4; mi++) {
        int r0 = bm * 128 + wm * 64 + mi * 16 + g;
#pragma unroll
        for (int ni = 0; ni < 4; ni++) {
            int c0 = bn * 128 + wn * 32 + ni * 8 + 2 * q;
            if (MODE == 0) {
                float v0 = acc[mi][ni][0] * scale, v1 = acc[mi][ni][1] * scale;
                float v2 = acc[mi][ni][2] * scale, v3 = acc[mi][ni][3] * scale;
                *(float2*)&g_scores[(size_t)r0 * NQ + c0]       = make_float2(v0, v1);
                *(float2*)&g_scores[(size_t)(r0 + 8) * NQ + c0] = make_float2(v2, v3);
                if (bm != bn) {   // symmetric mirror
                    g_scores[(size_t)c0 * NQ + r0]           = v0;
                    g_scores[(size_t)(c0 + 1) * NQ + r0]     = v1;
                    g_scores[(size_t)c0 * NQ + r0 + 8]       = v2;
                    g_scores[(size_t)(c0 + 1) * NQ + r0 + 8] = v3;
                }
            } else {
                size_t base = (c0 < 128) ? 0 : ((size_t)NQ * 128 - 128);
                atomicAdd(&Cout[base + (size_t)r0 * 128 + c0], acc[mi][ni][0]);
                atomicAdd(&Cout[base + (size_t)r0 * 128 + c0 + 1], acc[mi][ni][1]);
                atomicAdd(&Cout[base + (size_t)(r0 + 8) * 128 + c0], acc[mi][ni][2]);
                atomicAdd(&Cout[base + (size_t)(r0 + 8) * 128 + c0 + 1], acc[mi][ni][3]);
            }
        }
    }
}

// ---------------- K3: edge bias MLP + scatter-add onto scores (edge_index is int32) ----
__global__ void bias_kernel(const int* __restrict__ ei, const float* __restrict__ rbf,
                            const float* __restrict__ W1, const float* __restrict__ b1,
                            const float* __restrict__ W2, const float* __restrict__ b2) {
    __shared__ float sW1[EDIM * HID];
    __shared__ float sb1[HID], sW2[HID];
    __shared__ float sb2;
    for (int t = threadIdx.x; t < EDIM * HID; t += blockDim.x) sW1[t] = W1[t];
    if (threadIdx.x < HID) { sb1[threadIdx.x] = b1[threadIdx.x]; sW2[threadIdx.x] = W2[threadIdx.x]; }
    if (threadIdx.x == 0) sb2 = b2[0];
    __syncthreads();

    int e = blockIdx.x * blockDim.x + threadIdx.x;
    if (e >= EQ) return;

    float h[HID];
#pragma unroll
    for (int j = 0; j < HID; j++) h[j] = sb1[j];
    const float* r = rbf + (size_t)e * EDIM;
    for (int k = 0; k < EDIM; k++) {
        float rv = __ldg(&r[k]);
#pragma unroll
        for (int j = 0; j < HID; j++) h[j] = fmaf(rv, sW1[k * HID + j], h[j]);
    }
    float bias = sb2;
#pragma unroll
    for (int j = 0; j < HID; j++) {
        float x = h[j];
        float si = x / (1.f + __expf(-x));   // SiLU
        bias = fmaf(si, sW2[j], bias);
    }
    int i  = ei[e];
    int jn = ei[EQ + e];
    atomicAdd(&g_scores[(size_t)i * NQ + jn], bias);
}

// ---------------- K4: row softmax, register-resident ----------------
__global__ __launch_bounds__(256)
void softmax_kernel() {
    __shared__ float red[8];
    const int row = blockIdx.x, tid = threadIdx.x;
    const float4* src = (const float4*)(g_scores + (size_t)row * NQ);

    float4 v[8];
    float m = -1e30f;
#pragma unroll
    for (int i = 0; i < 8; i++) {
        v[i] = src[tid + i * 256];
        m = fmaxf(m, fmaxf(fmaxf(v[i].x, v[i].y), fmaxf(v[i].z, v[i].w)));
    }
#pragma unroll
    for (int o = 16; o; o >>= 1) m = fmaxf(m, __shfl_xor_sync(0xffffffffu, m, o));
    if ((tid & 31) == 0) red[tid >> 5] = m;
    __syncthreads();
    float bm = red[0];
#pragma unroll
    for (int w = 1; w < 8; w++) bm = fmaxf(bm, red[w]);
    __syncthreads();

    float sum = 0.f;
#pragma unroll
    for (int i = 0; i < 8; i++) {
        v[i].x = __expf(v[i].x - bm); v[i].y = __expf(v[i].y - bm);
        v[i].z = __expf(v[i].z - bm); v[i].w = __expf(v[i].w - bm);
        sum += v[i].x + v[i].y + v[i].z + v[i].w;
    }
#pragma unroll
    for (int o = 16; o; o >>= 1) sum += __shfl_xor_sync(0xffffffffu, sum, o);
    if ((tid & 31) == 0) red[tid >> 5] = sum;
    __syncthreads();
    float tot = 0.f;
#pragma unroll
    for (int w = 0; w < 8; w++) tot += red[w];
    const float inv = 1.f / tot;

    uint2* dst = (uint2*)(g_attn + (size_t)row * NQ);
#pragma unroll
    for (int i = 0; i < 8; i++) {
        __half2 lo = __floats2half2_rn(v[i].x * inv, v[i].y * inv);
        __half2 hi = __floats2half2_rn(v[i].z * inv, v[i].w * inv);
        uint2 o;
        o.x = *(unsigned*)&lo;
        o.y = *(unsigned*)&hi;
        dst[tid + i * 256] = o;
    }
}

// ---------------- K5: zero output (required before atomic split-K epilogue) ----------
__global__ void zero_kernel(float* __restrict__ out) {
    out[(size_t)blockIdx.x * 256 + threadIdx.x] = 0.f;
}

// ---------------- launch ----------------
extern "C" void kernel_launch(void* const* d_in, const int* in_sizes, int n_in,
                              void* d_out, int out_size) {
    const float* mag   = (const float*)d_in[0];
    const float* phase = (const float*)d_in[1];
    const int*   ei    = (const int*)d_in[2];
    const float* rbf   = (const float*)d_in[3];
    const float* W1    = (const float*)d_in[4];
    const float* b1    = (const float*)d_in[5];
    const float* W2    = (const float*)d_in[6];
    const float* b2    = (const float*)d_in[7];
    float*       out   = (float*)d_out;

    const float inv_sqrt_d = 0.08838834764831843f;   // 1/sqrt(128)
    const int smem0 = 2 * 3 * TSZ * (int)sizeof(__half);   // 110592
    const int smem1 = 2 * 2 * TSZ * (int)sizeof(__half);   // 73728

    cudaFuncSetAttribute(gemm_kernel<0>, cudaFuncAttributeMaxDynamicSharedMemorySize, smem0);
    cudaFuncSetAttribute(gemm_kernel<1>, cudaFuncAttributeMaxDynamicSharedMemorySize, smem1);

    prep_kernel<<<(NQ * DQ) / 256, 256>>>(mag, phase);
    gemm_kernel<0><<<dim3(NQ / 128, NQ / 128), 256, smem0>>>(nullptr, inv_sqrt_d);
    bias_kernel<<<EQ / 256, 256>>>(ei, rbf, W1, b1, W2, b2);
    softmax_kernel<<<NQ, 256>>>();
    zero_kernel<<<(NQ * 256) / 256, 256>>>(out);
    gemm_kernel<1><<<dim3(2, NQ / 128, 4), 256, smem1>>>(out, 1.0f);
}

// round 11
// speedup vs baseline: 2.0795x; 1.1299x over previous
#include <cuda_runtime.h>
#include <cuda_fp16.h>
#include <math.h>
#include <stdint.h>

#define NQ 8192
#define DQ 128
#define EQ 262144
#define EDIM 50
#define HID 32

// ---------------- scratch (device globals: no allocation allowed) ----------------
__device__ float   g_scores [(size_t)NQ * NQ];    // 256 MiB fp32 logits
__device__ __half  g_attn   [(size_t)NQ * NQ];    // 128 MiB fp16 probabilities
__device__ __half  g_ab     [(size_t)NQ * 256];   // [N][a|b], K=256 (fp16)
__device__ __half  g_mpT    [(size_t)256 * NQ];   // [mag|phase]^T (fp16)

__device__ __forceinline__ uint32_t smem_u32(const void* p) {
    uint32_t a;
    asm("{ .reg .u64 t; cvta.to.shared.u64 t, %1; cvt.u32.u64 %0, t; }" : "=r"(a) : "l"(p));
    return a;
}
__device__ __forceinline__ void cp_async16(void* sdst, const void* gsrc) {
    unsigned s = (unsigned)__cvta_generic_to_shared(sdst);
    asm volatile("cp.async.cg.shared.global [%0], [%1], 16;\n" :: "r"(s), "l"(gsrc));
}
#define CP_COMMIT() asm volatile("cp.async.commit_group;\n" ::: "memory")
#define CP_WAIT1()  asm volatile("cp.async.wait_group 1;\n" ::: "memory")

__device__ __forceinline__ void ldmx4(uint32_t* r, uint32_t addr) {
    asm volatile("ldmatrix.sync.aligned.m8n8.x4.shared.b16 {%0,%1,%2,%3}, [%4];"
                 : "=r"(r[0]), "=r"(r[1]), "=r"(r[2]), "=r"(r[3]) : "r"(addr));
}

// ---------------- K1: prep a,b (fp16) and transposed mag/phase (fp16) -------
__global__ void prep_kernel(const float* __restrict__ mag, const float* __restrict__ phase) {
    int idx = blockIdx.x * blockDim.x + threadIdx.x;   // < N*D
    int i = idx >> 7;
    int d = idx & 127;
    float m = mag[idx];
    float p = phase[idx];
    float s, c;
    __sincosf(p, &s, &c);
    g_ab[(size_t)i * 256 + d]         = __float2half_rn(m * c);
    g_ab[(size_t)i * 256 + 128 + d]   = __float2half_rn(m * s);
    g_mpT[(size_t)d * NQ + i]         = __float2half_rn(m);
    g_mpT[(size_t)(128 + d) * NQ + i] = __float2half_rn(p);
}

// ---------------- GEMM (fp16, fp32 accum): BM=BN=128, BK=64, 8 warps 2x4, m16n8k16 ------
// 2 smem tensors (A,B), 1 MMA term, cp.async double buffer, ldmatrix.x4 fragments.
// MODE 0: A=g_ab[bm], B=g_ab[bn]; K=256, C=g_scores*scale;
//         SYMMETRIC: bm<=bn tiles only + mirrored store.
// MODE 1: A=g_attn[bm], B=g_mpT[bn]; K=8192 split-K z=4, atomicAdd into Cout.
#define TSTRIDE 72
#define TSZ (128 * TSTRIDE)
#define TSZB (TSZ * 2)

template <int MODE>
__global__ __launch_bounds__(256)
void gemm_kernel(float* __restrict__ Cout, float scale) {
    extern __shared__ __align__(16) __half dsm[];   // [2 stages][2 tensors][128][72]

    const int bm = blockIdx.y, bn = blockIdx.x;
    if (MODE == 0 && bn < bm) return;   // symmetric: upper-triangle tiles only

    const int K = (MODE == 0) ? 256 : NQ;
    const __half* T0 = (MODE == 0) ? (g_ab  + (size_t)bm * 128 * K)
                                   : (g_attn + (size_t)bm * 128 * K);
    const __half* T1 = (MODE == 0) ? (g_ab  + (size_t)bn * 128 * K)
                                   : (g_mpT + (size_t)bn * 128 * K);

    const int tid = threadIdx.x;
    const int warp = tid >> 5, lane = tid & 31;
    const int wm = warp >> 2, wn = warp & 3;
    const int g = lane >> 2, q = lane & 3;

    float acc[4][4][4];
#pragma unroll
    for (int mi = 0; mi < 4; mi++)
#pragma unroll
        for (int ni = 0; ni < 4; ni++)
#pragma unroll
            for (int r = 0; r < 4; r++) acc[mi][ni][r] = 0.f;

    const int kbeg = (MODE == 0) ? 0 : blockIdx.z * (NQ / 4);
    const int nit = ((MODE == 0) ? 256 : NQ / 4) / 64;

    // ldmatrix per-lane byte offsets (row stride 144 B)
    const int xr = lane & 7;
    const int xb = (lane >> 3) & 1;
    const int xk = (lane >> 4) & 1;
    uint32_t aoff[4], boff[2];
#pragma unroll
    for (int mi = 0; mi < 4; mi++)
        aoff[mi] = (uint32_t)((wm * 64 + mi * 16 + xb * 8 + xr) * (TSTRIDE * 2) + xk * 16);
#pragma unroll
    for (int pi = 0; pi < 2; pi++)
        boff[pi] = (uint32_t)((wn * 32 + pi * 16 + xb * 8 + xr) * (TSTRIDE * 2) + xk * 16);

    const uint32_t smbase = smem_u32(dsm);

    // Fill one stage: per tensor 128 rows x 8 chunks(16B) = 1024 units; 4 per thread.
#define PREFETCH(IT, ST)                                                         \
    do {                                                                         \
        int k0_ = kbeg + (IT) * 64;                                              \
        __half* d_ = dsm + (ST) * 2 * TSZ;                                       \
        _Pragma("unroll")                                                        \
        for (int i_ = 0; i_ < 4; i_++) {                                         \
            int u_ = tid + i_ * 256;                                             \
            int r_ = u_ >> 3, c_ = (u_ & 7) * 8;                                 \
            size_t go_ = (size_t)r_ * K + k0_ + c_;                              \
            int so_ = r_ * TSTRIDE + c_;                                         \
            cp_async16(d_ + 0 * TSZ + so_, T0 + go_);                            \
            cp_async16(d_ + 1 * TSZ + so_, T1 + go_);                            \
        }                                                                        \
    } while (0)

    PREFETCH(0, 0);
    CP_COMMIT();

    for (int it = 0; it < nit; it++) {
        if (it + 1 < nit) PREFETCH(it + 1, (it + 1) & 1);
        CP_COMMIT();
        CP_WAIT1();
        __syncthreads();

        const uint32_t S0 = smbase + (uint32_t)(it & 1) * 2 * TSZB;
        const uint32_t S1 = S0 + TSZB;

#pragma unroll
        for (int kk = 0; kk < 4; kk++) {
            const uint32_t kb = kk * 32;
            uint32_t ra[4][4], rb[2][4];
#pragma unroll
            for (int mi = 0; mi < 4; mi++) ldmx4(ra[mi], S0 + aoff[mi] + kb);
#pragma unroll
            for (int pi = 0; pi < 2; pi++) ldmx4(rb[pi], S1 + boff[pi] + kb);

#pragma unroll
            for (int mi = 0; mi < 4; mi++)
#pragma unroll
                for (int ni = 0; ni < 4; ni++) {
                    const int pi = ni >> 1, h = ni & 1;
                    asm volatile(
                        "mma.sync.aligned.m16n8k16.row.col.f32.f16.f16.f32 "
                        "{%0,%1,%2,%3}, {%4,%5,%6,%7}, {%8,%9}, {%0,%1,%2,%3};\n"
                        : "+f"(acc[mi][ni][0]), "+f"(acc[mi][ni][1]),
                          "+f"(acc[mi][ni][2]), "+f"(acc[mi][ni][3])
                        : "r"(ra[mi][0]), "r"(ra[mi][1]), "r"(ra[mi][2]), "r"(ra[mi][3]),
                          "r"(rb[pi][h]), "r"(rb[pi][h + 2]));
                }
        }
        __syncthreads();
    }
#undef PREFETCH

    // epilogue
#pragma unroll
    for (int mi = 0; mi < 4; mi++) {
        int r0 = bm * 128 + wm * 64 + mi * 16 + g;
#pragma unroll
        for (int ni = 0; ni < 4; ni++) {
            int c0 = bn * 128 + wn * 32 + ni * 8 + 2 * q;
            if (MODE == 0) {
                float v0 = acc[mi][ni][0] * scale, v1 = acc[mi][ni][1] * scale;
                float v2 = acc[mi][ni][2] * scale, v3 = acc[mi][ni][3] * scale;
                *(float2*)&g_scores[(size_t)r0 * NQ + c0]       = make_float2(v0, v1);
                *(float2*)&g_scores[(size_t)(r0 + 8) * NQ + c0] = make_float2(v2, v3);
                if (bm != bn) {   // symmetric mirror
                    g_scores[(size_t)c0 * NQ + r0]           = v0;
                    g_scores[(size_t)(c0 + 1) * NQ + r0]     = v1;
                    g_scores[(size_t)c0 * NQ + r0 + 8]       = v2;
                    g_scores[(size_t)(c0 + 1) * NQ + r0 + 8] = v3;
                }
            } else {
                size_t base = (c0 < 128) ? 0 : ((size_t)NQ * 128 - 128);
                atomicAdd(&Cout[base + (size_t)r0 * 128 + c0], acc[mi][ni][0]);
                atomicAdd(&Cout[base + (size_t)r0 * 128 + c0 + 1], acc[mi][ni][1]);
                atomicAdd(&Cout[base + (size_t)(r0 + 8) * 128 + c0], acc[mi][ni][2]);
                atomicAdd(&Cout[base + (size_t)(r0 + 8) * 128 + c0 + 1], acc[mi][ni][3]);
            }
        }
    }
}

// ---------------- K3: edge bias MLP + scatter-add onto scores (edge_index is int32) ----
__global__ void bias_kernel(const int* __restrict__ ei, const float* __restrict__ rbf,
                            const float* __restrict__ W1, const float* __restrict__ b1,
                            const float* __restrict__ W2, const float* __restrict__ b2) {
    __shared__ float sW1[EDIM * HID];
    __shared__ float sb1[HID], sW2[HID];
    __shared__ float sb2;
    for (int t = threadIdx.x; t < EDIM * HID; t += blockDim.x) sW1[t] = W1[t];
    if (threadIdx.x < HID) { sb1[threadIdx.x] = b1[threadIdx.x]; sW2[threadIdx.x] = W2[threadIdx.x]; }
    if (threadIdx.x == 0) sb2 = b2[0];
    __syncthreads();

    int e = blockIdx.x * blockDim.x + threadIdx.x;
    if (e >= EQ) return;

    float h[HID];
#pragma unroll
    for (int j = 0; j < HID; j++) h[j] = sb1[j];
    const float* r = rbf + (size_t)e * EDIM;
    for (int k = 0; k < EDIM; k++) {
        float rv = __ldg(&r[k]);
#pragma unroll
        for (int j = 0; j < HID; j++) h[j] = fmaf(rv, sW1[k * HID + j], h[j]);
    }
    float bias = sb2;
#pragma unroll
    for (int j = 0; j < HID; j++) {
        float x = h[j];
        float si = x / (1.f + __expf(-x));   // SiLU
        bias = fmaf(si, sW2[j], bias);
    }
    int i  = ei[e];
    int jn = ei[EQ + e];
    atomicAdd(&g_scores[(size_t)i * NQ + jn], bias);
}

// ---------------- K4: row softmax, register-resident ----------------
__global__ __launch_bounds__(256)
void softmax_kernel() {
    __shared__ float red[8];
    const int row = blockIdx.x, tid = threadIdx.x;
    const float4* src = (const float4*)(g_scores + (size_t)row * NQ);

    float4 v[8];
    float m = -1e30f;
#pragma unroll
    for (int i = 0; i < 8; i++) {
        v[i] = src[tid + i * 256];
        m = fmaxf(m, fmaxf(fmaxf(v[i].x, v[i].y), fmaxf(v[i].z, v[i].w)));
    }
#pragma unroll
    for (int o = 16; o; o >>= 1) m = fmaxf(m, __shfl_xor_sync(0xffffffffu, m, o));
    if ((tid & 31) == 0) red[tid >> 5] = m;
    __syncthreads();
    float bm = red[0];
#pragma unroll
    for (int w = 1; w < 8; w++) bm = fmaxf(bm, red[w]);
    __syncthreads();

    float sum = 0.f;
#pragma unroll
    for (int i = 0; i < 8; i++) {
        v[i].x = __expf(v[i].x - bm); v[i].y = __expf(v[i].y - bm);
        v[i].z = __expf(v[i].z - bm); v[i].w = __expf(v[i].w - bm);
        sum += v[i].x + v[i].y + v[i].z + v[i].w;
    }
#pragma unroll
    for (int o = 16; o; o >>= 1) sum += __shfl_xor_sync(0xffffffffu, sum, o);
    if ((tid & 31) == 0) red[tid >> 5] = sum;
    __syncthreads();
    float tot = 0.f;
#pragma unroll
    for (int w = 0; w < 8; w++) tot += red[w];
    const float inv = 1.f / tot;

    uint2* dst = (uint2*)(g_attn + (size_t)row * NQ);
#pragma unroll
    for (int i = 0; i < 8; i++) {
        __half2 lo = __floats2half2_rn(v[i].x * inv, v[i].y * inv);
        __half2 hi = __floats2half2_rn(v[i].z * inv, v[i].w * inv);
        uint2 o;
        o.x = *(unsigned*)&lo;
        o.y = *(unsigned*)&hi;
        dst[tid + i * 256] = o;
    }
}

// ---------------- K5: zero output (required before atomic split-K epilogue) ----------
__global__ void zero_kernel(float* __restrict__ out) {
    out[(size_t)blockIdx.x * 256 + threadIdx.x] = 0.f;
}

// ---------------- launch ----------------
extern "C" void kernel_launch(void* const* d_in, const int* in_sizes, int n_in,
                              void* d_out, int out_size) {
    const float* mag   = (const float*)d_in[0];
    const float* phase = (const float*)d_in[1];
    const int*   ei    = (const int*)d_in[2];
    const float* rbf   = (const float*)d_in[3];
    const float* W1    = (const float*)d_in[4];
    const float* b1    = (const float*)d_in[5];
    const float* W2    = (const float*)d_in[6];
    const float* b2    = (const float*)d_in[7];
    float*       out   = (float*)d_out;

    const float inv_sqrt_d = 0.08838834764831843f;   // 1/sqrt(128)
    const int smem_bytes = 2 * 2 * TSZ * (int)sizeof(__half);   // 73728

    cudaFuncSetAttribute(gemm_kernel<0>, cudaFuncAttributeMaxDynamicSharedMemorySize, smem_bytes);
    cudaFuncSetAttribute(gemm_kernel<1>, cudaFuncAttributeMaxDynamicSharedMemorySize, smem_bytes);

    prep_kernel<<<(NQ * DQ) / 256, 256>>>(mag, phase);
    gemm_kernel<0><<<dim3(NQ / 128, NQ / 128), 256, smem_bytes>>>(nullptr, inv_sqrt_d);
    bias_kernel<<<EQ / 256, 256>>>(ei, rbf, W1, b1, W2, b2);
    softmax_kernel<<<NQ, 256>>>();
    zero_kernel<<<(NQ * 256) / 256, 256>>>(out);
    gemm_kernel<1><<<dim3(2, NQ / 128, 4), 256, smem_bytes>>>(out, 1.0f);
}

// round 12
// speedup vs baseline: 2.0859x; 1.0031x over previous
#include <cuda_runtime.h>
#include <cuda_fp16.h>
#include <math.h>
#include <stdint.h>

#define NQ 8192
#define DQ 128
#define EQ 262144
#define EDIM 50
#define HID 32

// ---------------- scratch (device globals: no allocation allowed) ----------------
__device__ float   g_scores [(size_t)NQ * NQ];    // 256 MiB fp32 logits
__device__ __half  g_attn   [(size_t)NQ * NQ];    // 128 MiB fp16 probabilities
__device__ __half  g_ab     [(size_t)NQ * 256];   // [N][a|b], K=256 (fp16)
__device__ __half  g_mpT    [(size_t)256 * NQ];   // [mag|phase]^T (fp16)

__device__ __forceinline__ uint32_t smem_u32(const void* p) {
    uint32_t a;
    asm("{ .reg .u64 t; cvta.to.shared.u64 t, %1; cvt.u32.u64 %0, t; }" : "=r"(a) : "l"(p));
    return a;
}
__device__ __forceinline__ void cp_async16(void* sdst, const void* gsrc) {
    unsigned s = (unsigned)__cvta_generic_to_shared(sdst);
    asm volatile("cp.async.cg.shared.global [%0], [%1], 16;\n" :: "r"(s), "l"(gsrc));
}
#define CP_COMMIT() asm volatile("cp.async.commit_group;\n" ::: "memory")
#define CP_WAIT1()  asm volatile("cp.async.wait_group 1;\n" ::: "memory")

__device__ __forceinline__ void ldmx4(uint32_t* r, uint32_t addr) {
    asm volatile("ldmatrix.sync.aligned.m8n8.x4.shared.b16 {%0,%1,%2,%3}, [%4];"
                 : "=r"(r[0]), "=r"(r[1]), "=r"(r[2]), "=r"(r[3]) : "r"(addr));
}

// ---------------- K1: prep a,b (fp16) and transposed mag/phase (fp16) -------
__global__ void prep_kernel(const float* __restrict__ mag, const float* __restrict__ phase) {
    int idx = blockIdx.x * blockDim.x + threadIdx.x;   // < N*D
    int i = idx >> 7;
    int d = idx & 127;
    float m = mag[idx];
    float p = phase[idx];
    float s, c;
    __sincosf(p, &s, &c);
    g_ab[(size_t)i * 256 + d]         = __float2half_rn(m * c);
    g_ab[(size_t)i * 256 + 128 + d]   = __float2half_rn(m * s);
    g_mpT[(size_t)d * NQ + i]         = __float2half_rn(m);
    g_mpT[(size_t)(128 + d) * NQ + i] = __float2half_rn(p);
}

// ---------------- GEMM (fp16, fp32 accum): BM=128, BK=64, 8 warps, m16n8k16 ------
// cp.async double buffer, ldmatrix.x4 fragments, 1 MMA term.
// MODE 0: BN=128, warp tile 64x32. A=g_ab[bm], B=g_ab[bn]; K=256, C=g_scores*scale;
//         SYMMETRIC: bm<=bn tiles only + mirrored store.
// MODE 1: BN=256, warp tile 64x64. A=g_attn[bm], B=g_mpT (all 256 rows);
//         K=8192 split-K z=4, atomicAdd into Cout. attn read exactly once.
#define TSTRIDE 72

template <int MODE>
__global__ __launch_bounds__(256)
void gemm_kernel(float* __restrict__ Cout, float scale) {
    extern __shared__ __align__(16) __half dsm[];

    constexpr int NB   = (MODE == 0) ? 128 : 256;      // B rows per tile
    constexpr int NI   = (MODE == 0) ? 4 : 8;          // n sub-tiles per warp
    constexpr int ATSZ = 128 * TSTRIDE;                // A tile elems
    constexpr int BTSZ = NB * TSTRIDE;                 // B tile elems
    constexpr int STG  = ATSZ + BTSZ;                  // stage elems

    const int bm = blockIdx.y, bn = blockIdx.x;
    if (MODE == 0 && bn < bm) return;   // symmetric: upper-triangle tiles only

    const int K = (MODE == 0) ? 256 : NQ;
    const __half* T0 = (MODE == 0) ? (g_ab  + (size_t)bm * 128 * K)
                                   : (g_attn + (size_t)bm * 128 * K);
    const __half* T1 = (MODE == 0) ? (g_ab  + (size_t)bn * 128 * K) : g_mpT;

    const int tid = threadIdx.x;
    const int warp = tid >> 5, lane = tid & 31;
    const int wm = warp >> 2, wn = warp & 3;
    const int g = lane >> 2, q = lane & 3;

    float acc[4][NI][4];
#pragma unroll
    for (int mi = 0; mi < 4; mi++)
#pragma unroll
        for (int ni = 0; ni < NI; ni++)
#pragma unroll
            for (int r = 0; r < 4; r++) acc[mi][ni][r] = 0.f;

    const int kbeg = (MODE == 0) ? 0 : blockIdx.z * (NQ / 4);
    const int nit = ((MODE == 0) ? 256 : NQ / 4) / 64;

    // ldmatrix per-lane byte offsets (row stride 144 B)
    const int xr = lane & 7;
    const int xb = (lane >> 3) & 1;
    const int xk = (lane >> 4) & 1;
    uint32_t aoff[4], boff[NI / 2];
#pragma unroll
    for (int mi = 0; mi < 4; mi++)
        aoff[mi] = (uint32_t)((wm * 64 + mi * 16 + xb * 8 + xr) * (TSTRIDE * 2) + xk * 16);
#pragma unroll
    for (int pi = 0; pi < NI / 2; pi++)
        boff[pi] = (uint32_t)((wn * (NI * 8) + pi * 16 + xb * 8 + xr) * (TSTRIDE * 2) + xk * 16);

    const uint32_t smbase = smem_u32(dsm);

    // Fill one stage. A: 128x8 chunks(16B); B: NBx8 chunks.
#define PREFETCH(IT, ST)                                                         \
    do {                                                                         \
        int k0_ = kbeg + (IT) * 64;                                              \
        __half* d_ = dsm + (ST) * STG;                                           \
        _Pragma("unroll")                                                        \
        for (int i_ = 0; i_ < 4; i_++) {                                         \
            int u_ = tid + i_ * 256;                                             \
            int r_ = u_ >> 3, c_ = (u_ & 7) * 8;                                 \
            cp_async16(d_ + r_ * TSTRIDE + c_, T0 + (size_t)r_ * K + k0_ + c_);  \
        }                                                                        \
        _Pragma("unroll")                                                        \
        for (int i_ = 0; i_ < NB / 32; i_++) {                                   \
            int u_ = tid + i_ * 256;                                             \
            int r_ = u_ >> 3, c_ = (u_ & 7) * 8;                                 \
            cp_async16(d_ + ATSZ + r_ * TSTRIDE + c_,                            \
                       T1 + (size_t)r_ * K + k0_ + c_);                          \
        }                                                                        \
    } while (0)

    PREFETCH(0, 0);
    CP_COMMIT();

    for (int it = 0; it < nit; it++) {
        if (it + 1 < nit) PREFETCH(it + 1, (it + 1) & 1);
        CP_COMMIT();
        CP_WAIT1();
        __syncthreads();

        const uint32_t S0 = smbase + (uint32_t)(it & 1) * STG * 2;   // bytes = elems*2
        const uint32_t S1 = S0 + ATSZ * 2;

#pragma unroll
        for (int kk = 0; kk < 4; kk++) {
            const uint32_t kb = kk * 32;
            uint32_t ra[4][4], rb[NI / 2][4];
#pragma unroll
            for (int mi = 0; mi < 4; mi++) ldmx4(ra[mi], S0 + aoff[mi] + kb);
#pragma unroll
            for (int pi = 0; pi < NI / 2; pi++) ldmx4(rb[pi], S1 + boff[pi] + kb);

#pragma unroll
            for (int mi = 0; mi < 4; mi++)
#pragma unroll
                for (int ni = 0; ni < NI; ni++) {
                    const int pi = ni >> 1, h = ni & 1;
                    asm volatile(
                        "mma.sync.aligned.m16n8k16.row.col.f32.f16.f16.f32 "
                        "{%0,%1,%2,%3}, {%4,%5,%6,%7}, {%8,%9}, {%0,%1,%2,%3};\n"
                        : "+f"(acc[mi][ni][0]), "+f"(acc[mi][ni][1]),
                          "+f"(acc[mi][ni][2]), "+f"(acc[mi][ni][3])
                        : "r"(ra[mi][0]), "r"(ra[mi][1]), "r"(ra[mi][2]), "r"(ra[mi][3]),
                          "r"(rb[pi][h]), "r"(rb[pi][h + 2]));
                }
        }
        __syncthreads();
    }
#undef PREFETCH

    // epilogue
#pragma unroll
    for (int mi = 0; mi < 4; mi++) {
        int r0 = bm * 128 + wm * 64 + mi * 16 + g;
#pragma unroll
        for (int ni = 0; ni < NI; ni++) {
            if (MODE == 0) {
                int c0 = bn * 128 + wn * 32 + ni * 8 + 2 * q;
                float v0 = acc[mi][ni][0] * scale, v1 = acc[mi][ni][1] * scale;
                float v2 = acc[mi][ni][2] * scale, v3 = acc[mi][ni][3] * scale;
                *(float2*)&g_scores[(size_t)r0 * NQ + c0]       = make_float2(v0, v1);
                *(float2*)&g_scores[(size_t)(r0 + 8) * NQ + c0] = make_float2(v2, v3);
                if (bm != bn) {   // symmetric mirror
                    g_scores[(size_t)c0 * NQ + r0]           = v0;
                    g_scores[(size_t)(c0 + 1) * NQ + r0]     = v1;
                    g_scores[(size_t)c0 * NQ + r0 + 8]       = v2;
                    g_scores[(size_t)(c0 + 1) * NQ + r0 + 8] = v3;
                }
            } else {
                int c0 = wn * 64 + ni * 8 + 2 * q;    // 0..255
                size_t base = (c0 < 128) ? 0 : ((size_t)NQ * 128 - 128);
                atomicAdd(&Cout[base + (size_t)r0 * 128 + c0], acc[mi][ni][0]);
                atomicAdd(&Cout[base + (size_t)r0 * 128 + c0 + 1], acc[mi][ni][1]);
                atomicAdd(&Cout[base + (size_t)(r0 + 8) * 128 + c0], acc[mi][ni][2]);
                atomicAdd(&Cout[base + (size_t)(r0 + 8) * 128 + c0 + 1], acc[mi][ni][3]);
            }
        }
    }
}

// ---------------- K3: edge bias MLP + scatter-add onto scores (edge_index is int32) ----
__global__ void bias_kernel(const int* __restrict__ ei, const float* __restrict__ rbf,
                            const float* __restrict__ W1, const float* __restrict__ b1,
                            const float* __restrict__ W2, const float* __restrict__ b2) {
    __shared__ float sW1[EDIM * HID];
    __shared__ float sb1[HID], sW2[HID];
    __shared__ float sb2;
    for (int t = threadIdx.x; t < EDIM * HID; t += blockDim.x) sW1[t] = W1[t];
    if (threadIdx.x < HID) { sb1[threadIdx.x] = b1[threadIdx.x]; sW2[threadIdx.x] = W2[threadIdx.x]; }
    if (threadIdx.x == 0) sb2 = b2[0];
    __syncthreads();

    int e = blockIdx.x * blockDim.x + threadIdx.x;
    if (e >= EQ) return;

    float h[HID];
#pragma unroll
    for (int j = 0; j < HID; j++) h[j] = sb1[j];
    const float* r = rbf + (size_t)e * EDIM;
    for (int k = 0; k < EDIM; k++) {
        float rv = __ldg(&r[k]);
#pragma unroll
        for (int j = 0; j < HID; j++) h[j] = fmaf(rv, sW1[k * HID + j], h[j]);
    }
    float bias = sb2;
#pragma unroll
    for (int j = 0; j < HID; j++) {
        float x = h[j];
        float si = x / (1.f + __expf(-x));   // SiLU
        bias = fmaf(si, sW2[j], bias);
    }
    int i  = ei[e];
    int jn = ei[EQ + e];
    atomicAdd(&g_scores[(size_t)i * NQ + jn], bias);
}

// ---------------- K4: row softmax, register-resident ----------------
__global__ __launch_bounds__(256)
void softmax_kernel() {
    __shared__ float red[8];
    const int row = blockIdx.x, tid = threadIdx.x;
    const float4* src = (const float4*)(g_scores + (size_t)row * NQ);

    float4 v[8];
    float m = -1e30f;
#pragma unroll
    for (int i = 0; i < 8; i++) {
        v[i] = src[tid + i * 256];
        m = fmaxf(m, fmaxf(fmaxf(v[i].x, v[i].y), fmaxf(v[i].z, v[i].w)));
    }
#pragma unroll
    for (int o = 16; o; o >>= 1) m = fmaxf(m, __shfl_xor_sync(0xffffffffu, m, o));
    if ((tid & 31) == 0) red[tid >> 5] = m;
    __syncthreads();
    float bm = red[0];
#pragma unroll
    for (int w = 1; w < 8; w++) bm = fmaxf(bm, red[w]);
    __syncthreads();

    float sum = 0.f;
#pragma unroll
    for (int i = 0; i < 8; i++) {
        v[i].x = __expf(v[i].x - bm); v[i].y = __expf(v[i].y - bm);
        v[i].z = __expf(v[i].z - bm); v[i].w = __expf(v[i].w - bm);
        sum += v[i].x + v[i].y + v[i].z + v[i].w;
    }
#pragma unroll
    for (int o = 16; o; o >>= 1) sum += __shfl_xor_sync(0xffffffffu, sum, o);
    if ((tid & 31) == 0) red[tid >> 5] = sum;
    __syncthreads();
    float tot = 0.f;
#pragma unroll
    for (int w = 0; w < 8; w++) tot += red[w];
    const float inv = 1.f / tot;

    uint2* dst = (uint2*)(g_attn + (size_t)row * NQ);
#pragma unroll
    for (int i = 0; i < 8; i++) {
        __half2 lo = __floats2half2_rn(v[i].x * inv, v[i].y * inv);
        __half2 hi = __floats2half2_rn(v[i].z * inv, v[i].w * inv);
        uint2 o;
        o.x = *(unsigned*)&lo;
        o.y = *(unsigned*)&hi;
        dst[tid + i * 256] = o;
    }
}

// ---------------- K5: zero output (required before atomic split-K epilogue) ----------
__global__ void zero_kernel(float* __restrict__ out) {
    out[(size_t)blockIdx.x * 256 + threadIdx.x] = 0.f;
}

// ---------------- launch ----------------
extern "C" void kernel_launch(void* const* d_in, const int* in_sizes, int n_in,
                              void* d_out, int out_size) {
    const float* mag   = (const float*)d_in[0];
    const float* phase = (const float*)d_in[1];
    const int*   ei    = (const int*)d_in[2];
    const float* rbf   = (const float*)d_in[3];
    const float* W1    = (const float*)d_in[4];
    const float* b1    = (const float*)d_in[5];
    const float* W2    = (const float*)d_in[6];
    const float* b2    = (const float*)d_in[7];
    float*       out   = (float*)d_out;

    const float inv_sqrt_d = 0.08838834764831843f;   // 1/sqrt(128)
    const int smem0 = 2 * (128 + 128) * TSTRIDE * (int)sizeof(__half);   // 73728
    const int smem1 = 2 * (128 + 256) * TSTRIDE * (int)sizeof(__half);   // 110592

    cudaFuncSetAttribute(gemm_kernel<0>, cudaFuncAttributeMaxDynamicSharedMemorySize, smem0);
    cudaFuncSetAttribute(gemm_kernel<1>, cudaFuncAttributeMaxDynamicSharedMemorySize, smem1);

    prep_kernel<<<(NQ * DQ) / 256, 256>>>(mag, phase);
    gemm_kernel<0><<<dim3(NQ / 128, NQ / 128), 256, smem0>>>(nullptr, inv_sqrt_d);
    bias_kernel<<<EQ / 256, 256>>>(ei, rbf, W1, b1, W2, b2);
    softmax_kernel<<<NQ, 256>>>();
    zero_kernel<<<(NQ * 256) / 256, 256>>>(out);
    gemm_kernel<1><<<dim3(1, NQ / 128, 4), 256, smem1>>>(out, 1.0f);
}

// round 13
// speedup vs baseline: 2.1365x; 1.0242x over previous
#include <cuda_runtime.h>
#include <cuda_fp16.h>
#include <math.h>
#include <stdint.h>

#define NQ 8192
#define DQ 128
#define EQ 262144
#define EDIM 50
#define HID 32

// ---------------- scratch (device globals: no allocation allowed) ----------------
__device__ float   g_scores [(size_t)NQ * NQ];    // 256 MiB fp32 logits
__device__ __half  g_attn   [(size_t)NQ * NQ];    // 128 MiB fp16 probabilities
__device__ __half  g_ab     [(size_t)NQ * 256];   // [N][a|b], K=256 (fp16)
__device__ __half  g_mpT    [(size_t)256 * NQ];   // [mag|phase]^T (fp16)

__device__ __forceinline__ uint32_t smem_u32(const void* p) {
    uint32_t a;
    asm("{ .reg .u64 t; cvta.to.shared.u64 t, %1; cvt.u32.u64 %0, t; }" : "=r"(a) : "l"(p));
    return a;
}
__device__ __forceinline__ void cp_async16(void* sdst, const void* gsrc) {
    unsigned s = (unsigned)__cvta_generic_to_shared(sdst);
    asm volatile("cp.async.cg.shared.global [%0], [%1], 16;\n" :: "r"(s), "l"(gsrc));
}
#define CP_COMMIT() asm volatile("cp.async.commit_group;\n" ::: "memory")
#define CP_WAIT1()  asm volatile("cp.async.wait_group 1;\n" ::: "memory")

__device__ __forceinline__ void ldmx4(uint32_t* r, uint32_t addr) {
    asm volatile("ldmatrix.sync.aligned.m8n8.x4.shared.b16 {%0,%1,%2,%3}, [%4];"
                 : "=r"(r[0]), "=r"(r[1]), "=r"(r[2]), "=r"(r[3]) : "r"(addr));
}

// ---------------- K1: prep a,b (fp16) and transposed mag/phase (fp16) -------
__global__ void prep_kernel(const float* __restrict__ mag, const float* __restrict__ phase) {
    int idx = blockIdx.x * blockDim.x + threadIdx.x;   // < N*D
    int i = idx >> 7;
    int d = idx & 127;
    float m = mag[idx];
    float p = phase[idx];
    float s, c;
    __sincosf(p, &s, &c);
    g_ab[(size_t)i * 256 + d]         = __float2half_rn(m * c);
    g_ab[(size_t)i * 256 + 128 + d]   = __float2half_rn(m * s);
    g_mpT[(size_t)d * NQ + i]         = __float2half_rn(m);
    g_mpT[(size_t)(128 + d) * NQ + i] = __float2half_rn(p);
}

// ---------------- GEMM (fp16, fp32 accum): BM=128, BK=64, 8 warps, m16n8k16 ------
// cp.async double buffer, ldmatrix.x4 fragments, 1 MMA term.
// MODE 0: BN=128, warp tile 64x32, occ=2 (128-reg cap; 1-term fits without spills).
//         A=g_ab[bm], B=g_ab[bn]; K=256, C=g_scores*scale; SYMMETRIC upper tiles.
// MODE 1: BN=256, warp tile 64x64, occ=1. A=g_attn[bm], B=g_mpT;
//         K=8192 split-K z=4, atomicAdd into Cout.
#define TSTRIDE 72

template <int MODE>
__global__ __launch_bounds__(256, (MODE == 0) ? 2 : 1)
void gemm_kernel(float* __restrict__ Cout, float scale) {
    extern __shared__ __align__(16) __half dsm[];

    constexpr int NB   = (MODE == 0) ? 128 : 256;      // B rows per tile
    constexpr int NI   = (MODE == 0) ? 4 : 8;          // n sub-tiles per warp
    constexpr int ATSZ = 128 * TSTRIDE;                // A tile elems
    constexpr int BTSZ = NB * TSTRIDE;                 // B tile elems
    constexpr int STG  = ATSZ + BTSZ;                  // stage elems

    const int bm = blockIdx.y, bn = blockIdx.x;
    if (MODE == 0 && bn < bm) return;   // symmetric: upper-triangle tiles only

    const int K = (MODE == 0) ? 256 : NQ;
    const __half* T0 = (MODE == 0) ? (g_ab  + (size_t)bm * 128 * K)
                                   : (g_attn + (size_t)bm * 128 * K);
    const __half* T1 = (MODE == 0) ? (g_ab  + (size_t)bn * 128 * K) : g_mpT;

    const int tid = threadIdx.x;
    const int warp = tid >> 5, lane = tid & 31;
    const int wm = warp >> 2, wn = warp & 3;
    const int g = lane >> 2, q = lane & 3;

    float acc[4][NI][4];
#pragma unroll
    for (int mi = 0; mi < 4; mi++)
#pragma unroll
        for (int ni = 0; ni < NI; ni++)
#pragma unroll
            for (int r = 0; r < 4; r++) acc[mi][ni][r] = 0.f;

    const int kbeg = (MODE == 0) ? 0 : blockIdx.z * (NQ / 4);
    const int nit = ((MODE == 0) ? 256 : NQ / 4) / 64;

    // ldmatrix per-lane byte offsets (row stride 144 B)
    const int xr = lane & 7;
    const int xb = (lane >> 3) & 1;
    const int xk = (lane >> 4) & 1;
    uint32_t aoff[4], boff[NI / 2];
#pragma unroll
    for (int mi = 0; mi < 4; mi++)
        aoff[mi] = (uint32_t)((wm * 64 + mi * 16 + xb * 8 + xr) * (TSTRIDE * 2) + xk * 16);
#pragma unroll
    for (int pi = 0; pi < NI / 2; pi++)
        boff[pi] = (uint32_t)((wn * (NI * 8) + pi * 16 + xb * 8 + xr) * (TSTRIDE * 2) + xk * 16);

    const uint32_t smbase = smem_u32(dsm);

    // Fill one stage. A: 128x8 chunks(16B); B: NBx8 chunks.
#define PREFETCH(IT, ST)                                                         \
    do {                                                                         \
        int k0_ = kbeg + (IT) * 64;                                              \
        __half* d_ = dsm + (ST) * STG;                                           \
        _Pragma("unroll")                                                        \
        for (int i_ = 0; i_ < 4; i_++) {                                         \
            int u_ = tid + i_ * 256;                                             \
            int r_ = u_ >> 3, c_ = (u_ & 7) * 8;                                 \
            cp_async16(d_ + r_ * TSTRIDE + c_, T0 + (size_t)r_ * K + k0_ + c_);  \
        }                                                                        \
        _Pragma("unroll")                                                        \
        for (int i_ = 0; i_ < NB / 32; i_++) {                                   \
            int u_ = tid + i_ * 256;                                             \
            int r_ = u_ >> 3, c_ = (u_ & 7) * 8;                                 \
            cp_async16(d_ + ATSZ + r_ * TSTRIDE + c_,                            \
                       T1 + (size_t)r_ * K + k0_ + c_);                          \
        }                                                                        \
    } while (0)

    PREFETCH(0, 0);
    CP_COMMIT();

    for (int it = 0; it < nit; it++) {
        if (it + 1 < nit) PREFETCH(it + 1, (it + 1) & 1);
        CP_COMMIT();
        CP_WAIT1();
        __syncthreads();

        const uint32_t S0 = smbase + (uint32_t)(it & 1) * STG * 2;   // bytes = elems*2
        const uint32_t S1 = S0 + ATSZ * 2;

#pragma unroll
        for (int kk = 0; kk < 4; kk++) {
            const uint32_t kb = kk * 32;
            uint32_t ra[4][4], rb[NI / 2][4];
#pragma unroll
            for (int mi = 0; mi < 4; mi++) ldmx4(ra[mi], S0 + aoff[mi] + kb);
#pragma unroll
            for (int pi = 0; pi < NI / 2; pi++) ldmx4(rb[pi], S1 + boff[pi] + kb);

#pragma unroll
            for (int mi = 0; mi < 4; mi++)
#pragma unroll
                for (int ni = 0; ni < NI; ni++) {
                    const int pi = ni >> 1, h = ni & 1;
                    asm volatile(
                        "mma.sync.aligned.m16n8k16.row.col.f32.f16.f16.f32 "
                        "{%0,%1,%2,%3}, {%4,%5,%6,%7}, {%8,%9}, {%0,%1,%2,%3};\n"
                        : "+f"(acc[mi][ni][0]), "+f"(acc[mi][ni][1]),
                          "+f"(acc[mi][ni][2]), "+f"(acc[mi][ni][3])
                        : "r"(ra[mi][0]), "r"(ra[mi][1]), "r"(ra[mi][2]), "r"(ra[mi][3]),
                          "r"(rb[pi][h]), "r"(rb[pi][h + 2]));
                }
        }
        __syncthreads();
    }
#undef PREFETCH

    // epilogue
#pragma unroll
    for (int mi = 0; mi < 4; mi++) {
        int r0 = bm * 128 + wm * 64 + mi * 16 + g;
#pragma unroll
        for (int ni = 0; ni < NI; ni++) {
            if (MODE == 0) {
                int c0 = bn * 128 + wn * 32 + ni * 8 + 2 * q;
                float v0 = acc[mi][ni][0] * scale, v1 = acc[mi][ni][1] * scale;
                float v2 = acc[mi][ni][2] * scale, v3 = acc[mi][ni][3] * scale;
                *(float2*)&g_scores[(size_t)r0 * NQ + c0]       = make_float2(v0, v1);
                *(float2*)&g_scores[(size_t)(r0 + 8) * NQ + c0] = make_float2(v2, v3);
                if (bm != bn) {   // symmetric mirror
                    g_scores[(size_t)c0 * NQ + r0]           = v0;
                    g_scores[(size_t)(c0 + 1) * NQ + r0]     = v1;
                    g_scores[(size_t)c0 * NQ + r0 + 8]       = v2;
                    g_scores[(size_t)(c0 + 1) * NQ + r0 + 8] = v3;
                }
            } else {
                int c0 = wn * 64 + ni * 8 + 2 * q;    // 0..255
                size_t base = (c0 < 128) ? 0 : ((size_t)NQ * 128 - 128);
                atomicAdd(&Cout[base + (size_t)r0 * 128 + c0], acc[mi][ni][0]);
                atomicAdd(&Cout[base + (size_t)r0 * 128 + c0 + 1], acc[mi][ni][1]);
                atomicAdd(&Cout[base + (size_t)(r0 + 8) * 128 + c0], acc[mi][ni][2]);
                atomicAdd(&Cout[base + (size_t)(r0 + 8) * 128 + c0 + 1], acc[mi][ni][3]);
            }
        }
    }
}

// ---------------- K3: edge bias MLP + scatter-add onto scores (edge_index is int32) ----
__global__ void bias_kernel(const int* __restrict__ ei, const float* __restrict__ rbf,
                            const float* __restrict__ W1, const float* __restrict__ b1,
                            const float* __restrict__ W2, const float* __restrict__ b2) {
    __shared__ float sW1[EDIM * HID];
    __shared__ float sb1[HID], sW2[HID];
    __shared__ float sb2;
    for (int t = threadIdx.x; t < EDIM * HID; t += blockDim.x) sW1[t] = W1[t];
    if (threadIdx.x < HID) { sb1[threadIdx.x] = b1[threadIdx.x]; sW2[threadIdx.x] = W2[threadIdx.x]; }
    if (threadIdx.x == 0) sb2 = b2[0];
    __syncthreads();

    int e = blockIdx.x * blockDim.x + threadIdx.x;
    if (e >= EQ) return;

    float h[HID];
#pragma unroll
    for (int j = 0; j < HID; j++) h[j] = sb1[j];
    const float* r = rbf + (size_t)e * EDIM;
    for (int k = 0; k < EDIM; k++) {
        float rv = __ldg(&r[k]);
#pragma unroll
        for (int j = 0; j < HID; j++) h[j] = fmaf(rv, sW1[k * HID + j], h[j]);
    }
    float bias = sb2;
#pragma unroll
    for (int j = 0; j < HID; j++) {
        float x = h[j];
        float si = x / (1.f + __expf(-x));   // SiLU
        bias = fmaf(si, sW2[j], bias);
    }
    int i  = ei[e];
    int jn = ei[EQ + e];
    atomicAdd(&g_scores[(size_t)i * NQ + jn], bias);
}

// ---------------- K4: row softmax, register-resident ----------------
__global__ __launch_bounds__(256)
void softmax_kernel() {
    __shared__ float red[8];
    const int row = blockIdx.x, tid = threadIdx.x;
    const float4* src = (const float4*)(g_scores + (size_t)row * NQ);

    float4 v[8];
    float m = -1e30f;
#pragma unroll
    for (int i = 0; i < 8; i++) {
        v[i] = src[tid + i * 256];
        m = fmaxf(m, fmaxf(fmaxf(v[i].x, v[i].y), fmaxf(v[i].z, v[i].w)));
    }
#pragma unroll
    for (int o = 16; o; o >>= 1) m = fmaxf(m, __shfl_xor_sync(0xffffffffu, m, o));
    if ((tid & 31) == 0) red[tid >> 5] = m;
    __syncthreads();
    float bm = red[0];
#pragma unroll
    for (int w = 1; w < 8; w++) bm = fmaxf(bm, red[w]);
    __syncthreads();

    float sum = 0.f;
#pragma unroll
    for (int i = 0; i < 8; i++) {
        v[i].x = __expf(v[i].x - bm); v[i].y = __expf(v[i].y - bm);
        v[i].z = __expf(v[i].z - bm); v[i].w = __expf(v[i].w - bm);
        sum += v[i].x + v[i].y + v[i].z + v[i].w;
    }
#pragma unroll
    for (int o = 16; o; o >>= 1) sum += __shfl_xor_sync(0xffffffffu, sum, o);
    if ((tid & 31) == 0) red[tid >> 5] = sum;
    __syncthreads();
    float tot = 0.f;
#pragma unroll
    for (int w = 0; w < 8; w++) tot += red[w];
    const float inv = 1.f / tot;

    uint2* dst = (uint2*)(g_attn + (size_t)row * NQ);
#pragma unroll
    for (int i = 0; i < 8; i++) {
        __half2 lo = __floats2half2_rn(v[i].x * inv, v[i].y * inv);
        __half2 hi = __floats2half2_rn(v[i].z * inv, v[i].w * inv);
        uint2 o;
        o.x = *(unsigned*)&lo;
        o.y = *(unsigned*)&hi;
        dst[tid + i * 256] = o;
    }
}

// ---------------- K5: zero output (required before atomic split-K epilogue) ----------
__global__ void zero_kernel(float* __restrict__ out) {
    out[(size_t)blockIdx.x * 256 + threadIdx.x] = 0.f;
}

// ---------------- launch ----------------
extern "C" void kernel_launch(void* const* d_in, const int* in_sizes, int n_in,
                              void* d_out, int out_size) {
    const float* mag   = (const float*)d_in[0];
    const float* phase = (const float*)d_in[1];
    const int*   ei    = (const int*)d_in[2];
    const float* rbf   = (const float*)d_in[3];
    const float* W1    = (const float*)d_in[4];
    const float* b1    = (const float*)d_in[5];
    const float* W2    = (const float*)d_in[6];
    const float* b2    = (const float*)d_in[7];
    float*       out   = (float*)d_out;

    const float inv_sqrt_d = 0.08838834764831843f;   // 1/sqrt(128)
    const int smem0 = 2 * (128 + 128) * TSTRIDE * (int)sizeof(__half);   // 73728
    const int smem1 = 2 * (128 + 256) * TSTRIDE * (int)sizeof(__half);   // 110592

    cudaFuncSetAttribute(gemm_kernel<0>, cudaFuncAttributeMaxDynamicSharedMemorySize, smem0);
    cudaFuncSetAttribute(gemm_kernel<1>, cudaFuncAttributeMaxDynamicSharedMemorySize, smem1);

    prep_kernel<<<(NQ * DQ) / 256, 256>>>(mag, phase);
    gemm_kernel<0><<<dim3(NQ / 128, NQ / 128), 256, smem0>>>(nullptr, inv_sqrt_d);
    bias_kernel<<<EQ / 256, 256>>>(ei, rbf, W1, b1, W2, b2);
    softmax_kernel<<<NQ, 256>>>();
    zero_kernel<<<(NQ * 256) / 256, 256>>>(out);
    gemm_kernel<1><<<dim3(1, NQ / 128, 4), 256, smem1>>>(out, 1.0f);
}